// round 1
// baseline (speedup 1.0000x reference)
#include <cuda_runtime.h>
#include <cuda_bf16.h>
#include <math.h>

// ---------------------------------------------------------------------------
// AttentionActPrune: full MHA block.
//   B=16, S=1024, d=1024, H=16, Dh=64
//   q = X@Wq^T + bq ; k,v likewise ; flash attention ; out = ctx@Wo^T + bo
// Round-1 baseline: fp32 scalar, tiled SGEMM + flash attention.
// ---------------------------------------------------------------------------

#define BATCH   16
#define SEQ     1024
#define DMODEL  1024
#define NHEAD   16
#define DHEAD   64
#define MROWS   (BATCH * SEQ)          // 16384

// Scratch (device globals: no allocation in kernel_launch)
__device__ float g_Q[(size_t)MROWS * DMODEL];
__device__ float g_K[(size_t)MROWS * DMODEL];
__device__ float g_V[(size_t)MROWS * DMODEL];
__device__ float g_C[(size_t)MROWS * DMODEL];

// ---------------------------------------------------------------------------
// GEMM (NT): C[m,n] = sum_k A[m,k] * B[n,k] + bias[n]
// A: [M,K] row-major, B: [N,K] row-major (torch Linear weight layout).
// 128x128 tile, BK=16, 256 threads, 8x8 per-thread register tile.
// M,N,K all multiples of the tile sizes here -> no bounds checks.
// ---------------------------------------------------------------------------
#define GBM 128
#define GBN 128
#define GBK 16
#define GTM 8
#define GTN 8

__global__ __launch_bounds__(256, 2)
void gemm_nt_bias(const float* __restrict__ A, const float* __restrict__ B,
                  const float* __restrict__ bias, float* __restrict__ C,
                  int M, int N, int K)
{
    __shared__ float As[GBK][GBM];
    __shared__ float Bs[GBK][GBN];

    const int tid = threadIdx.x;
    const int bm = blockIdx.y * GBM;
    const int bn = blockIdx.x * GBN;
    const int tx = tid & 15;          // 0..15  -> N direction
    const int ty = tid >> 4;          // 0..15  -> M direction

    float acc[GTM][GTN];
#pragma unroll
    for (int i = 0; i < GTM; i++)
#pragma unroll
        for (int j = 0; j < GTN; j++) acc[i][j] = 0.f;

    for (int k0 = 0; k0 < K; k0 += GBK) {
        // Load A tile: 128 rows x 16 k = 512 float4, 2 per thread, transposed store
#pragma unroll
        for (int i = 0; i < 2; i++) {
            int idx = tid + i * 256;            // 0..511
            int r = idx >> 2;                    // row in tile
            int c4 = (idx & 3) << 2;             // k offset (0,4,8,12)
            float4 v = *(const float4*)(A + (size_t)(bm + r) * K + k0 + c4);
            As[c4 + 0][r] = v.x; As[c4 + 1][r] = v.y;
            As[c4 + 2][r] = v.z; As[c4 + 3][r] = v.w;
        }
#pragma unroll
        for (int i = 0; i < 2; i++) {
            int idx = tid + i * 256;
            int r = idx >> 2;
            int c4 = (idx & 3) << 2;
            float4 v = *(const float4*)(B + (size_t)(bn + r) * K + k0 + c4);
            Bs[c4 + 0][r] = v.x; Bs[c4 + 1][r] = v.y;
            Bs[c4 + 2][r] = v.z; Bs[c4 + 3][r] = v.w;
        }
        __syncthreads();

#pragma unroll
        for (int k = 0; k < GBK; k++) {
            float ra[GTM], rb[GTN];
#pragma unroll
            for (int i = 0; i < GTM; i++) ra[i] = As[k][ty * GTM + i];
#pragma unroll
            for (int j = 0; j < GTN; j++) rb[j] = Bs[k][tx * GTN + j];
#pragma unroll
            for (int i = 0; i < GTM; i++)
#pragma unroll
                for (int j = 0; j < GTN; j++)
                    acc[i][j] = fmaf(ra[i], rb[j], acc[i][j]);
        }
        __syncthreads();
    }

    // Epilogue: add bias, store
#pragma unroll
    for (int i = 0; i < GTM; i++) {
        float* crow = C + (size_t)(bm + ty * GTM + i) * N + bn + tx * GTN;
#pragma unroll
        for (int j = 0; j < GTN; j++)
            crow[j] = acc[i][j] + bias[bn + tx * GTN + j];
    }
}

// ---------------------------------------------------------------------------
// Flash attention: one CTA per (batch, head, 64-query block).
// 256 threads. Online softmax, O accumulators in registers (4x4 per thread).
// Smem layouts (padded stride 65 for conflict-free column access):
//   Qs[d*65 + q], Ks[d*65 + n], Vs[n*65 + d], Ps[n*65 + q]
// ---------------------------------------------------------------------------
#define ATT_SMEM_FLOATS (4 * 64 * 65 + 3 * 64)

__global__ __launch_bounds__(256, 3)
void attention_kernel(const float* __restrict__ Q, const float* __restrict__ K,
                      const float* __restrict__ V, float* __restrict__ C)
{
    extern __shared__ float smem[];
    float* Qs   = smem;                    // 64*65
    float* Ks   = Qs + 64 * 65;
    float* Vs   = Ks + 64 * 65;
    float* Ps   = Vs + 64 * 65;
    float* rowm = Ps + 64 * 65;            // 64
    float* rowl = rowm + 64;
    float* rowa = rowl + 64;

    const int tid = threadIdx.x;
    const int qb  = blockIdx.x;            // 0..15
    const int h   = blockIdx.y;            // 0..15
    const int b   = blockIdx.z;            // 0..15

    // base offset of (b, row s, head h, dim 0) with row stride DMODEL
    const size_t base = (size_t)b * SEQ * DMODEL + (size_t)h * DHEAD;

    // Load Q block transposed: Qs[d*65 + q]
    for (int idx = tid; idx < 64 * 64; idx += 256) {
        int q = idx >> 6, d = idx & 63;
        Qs[d * 65 + q] = Q[base + (size_t)(qb * 64 + q) * DMODEL + d];
    }
    if (tid < 64) { rowm[tid] = -1e30f; rowl[tid] = 0.f; }

    const int rr = tid >> 4;               // 0..15 (query quad)
    const int cc = tid & 15;               // 0..15 (col quad)
    float o[4][4];
#pragma unroll
    for (int i = 0; i < 4; i++)
#pragma unroll
        for (int j = 0; j < 4; j++) o[i][j] = 0.f;

    __syncthreads();

    for (int kb = 0; kb < SEQ / 64; kb++) {
        // Load K (transposed) and V (direct) tiles
        for (int idx = tid; idx < 64 * 64; idx += 256) {
            int n = idx >> 6, d = idx & 63;
            size_t g = base + (size_t)(kb * 64 + n) * DMODEL + d;
            Ks[d * 65 + n] = K[g];
            Vs[n * 65 + d] = V[g];
        }
        __syncthreads();

        // S = Q @ K^T  (4x4 register tile per thread)
        float s[4][4];
#pragma unroll
        for (int i = 0; i < 4; i++)
#pragma unroll
            for (int j = 0; j < 4; j++) s[i][j] = 0.f;

#pragma unroll 8
        for (int d = 0; d < DHEAD; d++) {
            float qv[4], kv[4];
#pragma unroll
            for (int i = 0; i < 4; i++) qv[i] = Qs[d * 65 + rr * 4 + i];
#pragma unroll
            for (int j = 0; j < 4; j++) kv[j] = Ks[d * 65 + cc * 4 + j];
#pragma unroll
            for (int i = 0; i < 4; i++)
#pragma unroll
                for (int j = 0; j < 4; j++)
                    s[i][j] = fmaf(qv[i], kv[j], s[i][j]);
        }
        // Write scores transposed: Ps[kcol*65 + qrow], scaled by 1/sqrt(Dh)
#pragma unroll
        for (int i = 0; i < 4; i++)
#pragma unroll
            for (int j = 0; j < 4; j++)
                Ps[(cc * 4 + j) * 65 + rr * 4 + i] = s[i][j] * 0.125f;
        __syncthreads();

        // Online softmax: 4 threads per query row
        {
            const int row = tid >> 2;       // 0..63
            const int l   = tid & 3;        // 0..3, consecutive lanes in a warp
            float vals[16];
            float m = -1e30f;
#pragma unroll
            for (int c = 0; c < 16; c++) {
                vals[c] = Ps[(l * 16 + c) * 65 + row];
                m = fmaxf(m, vals[c]);
            }
            m = fmaxf(m, __shfl_xor_sync(0xffffffffu, m, 1));
            m = fmaxf(m, __shfl_xor_sync(0xffffffffu, m, 2));
            const float mold = rowm[row];
            const float mnew = fmaxf(mold, m);
            float sum = 0.f;
#pragma unroll
            for (int c = 0; c < 16; c++) {
                float p = __expf(vals[c] - mnew);
                Ps[(l * 16 + c) * 65 + row] = p;
                sum += p;
            }
            sum += __shfl_xor_sync(0xffffffffu, sum, 1);
            sum += __shfl_xor_sync(0xffffffffu, sum, 2);
            if (l == 0) {
                float a = __expf(mold - mnew);
                rowa[row] = a;
                rowm[row] = mnew;
                rowl[row] = rowl[row] * a + sum;
            }
        }
        __syncthreads();

        // O = O * alpha + P @ V   (4 q-rows x 4 d-cols per thread)
        float a[4];
#pragma unroll
        for (int i = 0; i < 4; i++) a[i] = rowa[rr * 4 + i];
#pragma unroll
        for (int i = 0; i < 4; i++)
#pragma unroll
            for (int j = 0; j < 4; j++) o[i][j] *= a[i];

#pragma unroll 8
        for (int n = 0; n < 64; n++) {
            float pv[4], vv[4];
#pragma unroll
            for (int i = 0; i < 4; i++) pv[i] = Ps[n * 65 + rr * 4 + i];
#pragma unroll
            for (int j = 0; j < 4; j++) vv[j] = Vs[n * 65 + cc * 4 + j];
#pragma unroll
            for (int i = 0; i < 4; i++)
#pragma unroll
                for (int j = 0; j < 4; j++)
                    o[i][j] = fmaf(pv[i], vv[j], o[i][j]);
        }
        __syncthreads();   // protect Ks/Vs/Ps before next iteration's loads
    }

    // Normalize and write ctx back in [b, s, h*64+d] layout (GEMM-ready)
    float linv[4];
#pragma unroll
    for (int i = 0; i < 4; i++) linv[i] = 1.f / rowl[rr * 4 + i];
#pragma unroll
    for (int i = 0; i < 4; i++) {
        float* crow = C + base + (size_t)(qb * 64 + rr * 4 + i) * DMODEL + cc * 4;
#pragma unroll
        for (int j = 0; j < 4; j++)
            crow[j] = o[i][j] * linv[i];
    }
}

// ---------------------------------------------------------------------------
// Launch
// ---------------------------------------------------------------------------
extern "C" void kernel_launch(void* const* d_in, const int* in_sizes, int n_in,
                              void* d_out, int out_size)
{
    const float* X  = (const float*)d_in[0];
    const float* Wq = (const float*)d_in[1];
    const float* bq = (const float*)d_in[2];
    const float* Wk = (const float*)d_in[3];
    const float* bk = (const float*)d_in[4];
    const float* Wv = (const float*)d_in[5];
    const float* bv = (const float*)d_in[6];
    const float* Wo = (const float*)d_in[7];
    const float* bo = (const float*)d_in[8];
    float* out = (float*)d_out;

    float *Qp, *Kp, *Vp, *Cp;
    cudaGetSymbolAddress((void**)&Qp, g_Q);
    cudaGetSymbolAddress((void**)&Kp, g_K);
    cudaGetSymbolAddress((void**)&Vp, g_V);
    cudaGetSymbolAddress((void**)&Cp, g_C);

    static bool attr_set = false;
    if (!attr_set) {
        cudaFuncSetAttribute(attention_kernel,
                             cudaFuncAttributeMaxDynamicSharedMemorySize,
                             ATT_SMEM_FLOATS * (int)sizeof(float));
        attr_set = true;
    }

    dim3 gemm_grid(DMODEL / GBN, MROWS / GBM);   // (8, 128)
    gemm_nt_bias<<<gemm_grid, 256>>>(X, Wq, bq, Qp, MROWS, DMODEL, DMODEL);
    gemm_nt_bias<<<gemm_grid, 256>>>(X, Wk, bk, Kp, MROWS, DMODEL, DMODEL);
    gemm_nt_bias<<<gemm_grid, 256>>>(X, Wv, bv, Vp, MROWS, DMODEL, DMODEL);

    dim3 att_grid(SEQ / 64, NHEAD, BATCH);       // (16, 16, 16)
    attention_kernel<<<att_grid, 256, ATT_SMEM_FLOATS * sizeof(float)>>>(Qp, Kp, Vp, Cp);

    gemm_nt_bias<<<gemm_grid, 256>>>(Cp, Wo, bo, out, MROWS, DMODEL, DMODEL);
}

// round 3
// speedup vs baseline: 1.6925x; 1.6925x over previous
#include <cuda_runtime.h>
#include <cuda_bf16.h>
#include <cstdint>
#include <math.h>

// ---------------------------------------------------------------------------
// AttentionActPrune: full MHA block. B=16, S=1024, d=1024, H=16, Dh=64.
// Round 3: projection GEMMs via mma.sync tf32 (HMMA path — tcgen05 PTX is
//          rejected by this harness's sm_103 (non-'a') PTX target).
//          Flash attention unchanged.
// ---------------------------------------------------------------------------

#define BATCH   16
#define SEQ     1024
#define DMODEL  1024
#define NHEAD   16
#define DHEAD   64
#define MROWS   (BATCH * SEQ)          // 16384

__device__ float g_Q[(size_t)MROWS * DMODEL];
__device__ float g_K[(size_t)MROWS * DMODEL];
__device__ float g_V[(size_t)MROWS * DMODEL];
__device__ float g_C[(size_t)MROWS * DMODEL];

// ---------------------------------------------------------------------------
// tf32 GEMM (NT): C[m,n] = sum_k A[m,k]*B[n,k] + bias[n]
// CTA: 128x128 tile, 4 warps (128 thr), warp tile 64x64 (2x2 warp grid).
// BK=32. Smem stores tf32-converted elements with k-pair permutation:
//   within each 8-group, order is k = 0,4,1,5,2,6,3,7  (pos = 2*(k&3) + (k>>2))
// so each mma fragment (k and k+4) is ONE 8-byte LDS.
// Row stride 42 floats: staging STS conflict-free, fragment LDS ~conflict-free.
// ---------------------------------------------------------------------------
#define GK 32
#define SSTRIDE 42          // floats per smem row (even -> 8B-aligned pairs)

__device__ __forceinline__ uint32_t f2tf32(float f) {
    uint32_t u;
    asm("cvt.rna.tf32.f32 %0, %1;" : "=r"(u) : "f"(f));
    return u;
}

__device__ __forceinline__ void mma_tf32(float* c, uint32_t a0, uint32_t a1,
                                         uint32_t a2, uint32_t a3,
                                         uint32_t b0, uint32_t b1) {
    asm volatile(
        "mma.sync.aligned.m16n8k8.row.col.f32.tf32.tf32.f32 "
        "{%0,%1,%2,%3}, {%4,%5,%6,%7}, {%8,%9}, {%0,%1,%2,%3};"
        : "+f"(c[0]), "+f"(c[1]), "+f"(c[2]), "+f"(c[3])
        : "r"(a0), "r"(a1), "r"(a2), "r"(a3), "r"(b0), "r"(b1));
}

__global__ __launch_bounds__(128)
void gemm_tf32_nt(const float* __restrict__ A, const float* __restrict__ B,
                  const float* __restrict__ bias, float* __restrict__ C,
                  int M, int N, int K)
{
    __shared__ uint32_t sA[128 * SSTRIDE];
    __shared__ uint32_t sB[128 * SSTRIDE];

    const int tid  = threadIdx.x;
    const int wid  = tid >> 5;
    const int lane = tid & 31;
    const int g    = lane >> 2;       // 0..7
    const int tg   = lane & 3;        // 0..3

    const int warp_m = wid & 1;       // 2 warps along M
    const int warp_n = wid >> 1;      // 2 warps along N
    const int bm = blockIdx.y * 128;
    const int bn = blockIdx.x * 128;

    float acc[4][8][4];
#pragma unroll
    for (int i = 0; i < 4; i++)
#pragma unroll
        for (int j = 0; j < 8; j++)
#pragma unroll
            for (int q = 0; q < 4; q++) acc[i][j][q] = 0.f;

    for (int k0 = 0; k0 < K; k0 += GK) {
        // ---- stage 128x32 of A and B, tf32-converted, k-pair permuted ----
#pragma unroll
        for (int i = 0; i < 8; i++) {
            int idx = tid + i * 128;          // 0..1023
            int r = idx >> 3;                 // 0..127
            int c = idx & 7;                  // float4 index (k = 4c..4c+3)
            int base = r * SSTRIDE + (c >> 1) * 8 + (c & 1);
            float4 va = *(const float4*)(A + (size_t)(bm + r) * K + k0 + c * 4);
            sA[base + 0] = f2tf32(va.x);
            sA[base + 2] = f2tf32(va.y);
            sA[base + 4] = f2tf32(va.z);
            sA[base + 6] = f2tf32(va.w);
            float4 vb = *(const float4*)(B + (size_t)(bn + r) * K + k0 + c * 4);
            sB[base + 0] = f2tf32(vb.x);
            sB[base + 2] = f2tf32(vb.y);
            sB[base + 4] = f2tf32(vb.z);
            sB[base + 6] = f2tf32(vb.w);
        }
        __syncthreads();

        // ---- 4 k-steps of m16n8k8 ----
#pragma unroll
        for (int ks = 0; ks < 4; ks++) {
            const int kcol = ks * 8 + 2 * tg;
            uint2 aLo[4], aHi[4];
#pragma unroll
            for (int mt = 0; mt < 4; mt++) {
                int r = warp_m * 64 + mt * 16 + g;
                aLo[mt] = *(const uint2*)&sA[r * SSTRIDE + kcol];
                aHi[mt] = *(const uint2*)&sA[(r + 8) * SSTRIDE + kcol];
            }
            uint2 bf[8];
#pragma unroll
            for (int nt = 0; nt < 8; nt++) {
                int rn = warp_n * 64 + nt * 8 + g;
                bf[nt] = *(const uint2*)&sB[rn * SSTRIDE + kcol];
            }
#pragma unroll
            for (int mt = 0; mt < 4; mt++)
#pragma unroll
                for (int nt = 0; nt < 8; nt++)
                    mma_tf32(acc[mt][nt],
                             aLo[mt].x, aHi[mt].x, aLo[mt].y, aHi[mt].y,
                             bf[nt].x, bf[nt].y);
        }
        __syncthreads();
    }

    // ---- epilogue: bias + store (8B stores, 32B-sector aligned groups) ----
#pragma unroll
    for (int mt = 0; mt < 4; mt++) {
        const int row0 = bm + warp_m * 64 + mt * 16 + g;
#pragma unroll
        for (int nt = 0; nt < 8; nt++) {
            const int col = bn + warp_n * 64 + nt * 8 + 2 * tg;
            const float b0 = bias[col], b1 = bias[col + 1];
            float2 v0 = make_float2(acc[mt][nt][0] + b0, acc[mt][nt][1] + b1);
            float2 v1 = make_float2(acc[mt][nt][2] + b0, acc[mt][nt][3] + b1);
            *(float2*)(C + (size_t)row0 * N + col) = v0;
            *(float2*)(C + (size_t)(row0 + 8) * N + col) = v1;
        }
    }
}

// ---------------------------------------------------------------------------
// Flash attention (unchanged from round 1)
// ---------------------------------------------------------------------------
#define ATT_SMEM_FLOATS (4 * 64 * 65 + 3 * 64)

__global__ __launch_bounds__(256, 3)
void attention_kernel(const float* __restrict__ Q, const float* __restrict__ K,
                      const float* __restrict__ V, float* __restrict__ C)
{
    extern __shared__ float smem[];
    float* Qs   = smem;
    float* Ks   = Qs + 64 * 65;
    float* Vs   = Ks + 64 * 65;
    float* Ps   = Vs + 64 * 65;
    float* rowm = Ps + 64 * 65;
    float* rowl = rowm + 64;
    float* rowa = rowl + 64;

    const int tid = threadIdx.x;
    const int qb  = blockIdx.x;
    const int h   = blockIdx.y;
    const int b   = blockIdx.z;

    const size_t base = (size_t)b * SEQ * DMODEL + (size_t)h * DHEAD;

    for (int idx = tid; idx < 64 * 64; idx += 256) {
        int q = idx >> 6, d = idx & 63;
        Qs[d * 65 + q] = Q[base + (size_t)(qb * 64 + q) * DMODEL + d];
    }
    if (tid < 64) { rowm[tid] = -1e30f; rowl[tid] = 0.f; }

    const int rr = tid >> 4;
    const int cc = tid & 15;
    float o[4][4];
#pragma unroll
    for (int i = 0; i < 4; i++)
#pragma unroll
        for (int j = 0; j < 4; j++) o[i][j] = 0.f;

    __syncthreads();

    for (int kb = 0; kb < SEQ / 64; kb++) {
        for (int idx = tid; idx < 64 * 64; idx += 256) {
            int n = idx >> 6, d = idx & 63;
            size_t gaddr = base + (size_t)(kb * 64 + n) * DMODEL + d;
            Ks[d * 65 + n] = K[gaddr];
            Vs[n * 65 + d] = V[gaddr];
        }
        __syncthreads();

        float s[4][4];
#pragma unroll
        for (int i = 0; i < 4; i++)
#pragma unroll
            for (int j = 0; j < 4; j++) s[i][j] = 0.f;

#pragma unroll 8
        for (int d = 0; d < DHEAD; d++) {
            float qv[4], kv[4];
#pragma unroll
            for (int i = 0; i < 4; i++) qv[i] = Qs[d * 65 + rr * 4 + i];
#pragma unroll
            for (int j = 0; j < 4; j++) kv[j] = Ks[d * 65 + cc * 4 + j];
#pragma unroll
            for (int i = 0; i < 4; i++)
#pragma unroll
                for (int j = 0; j < 4; j++)
                    s[i][j] = fmaf(qv[i], kv[j], s[i][j]);
        }
#pragma unroll
        for (int i = 0; i < 4; i++)
#pragma unroll
            for (int j = 0; j < 4; j++)
                Ps[(cc * 4 + j) * 65 + rr * 4 + i] = s[i][j] * 0.125f;
        __syncthreads();

        {
            const int row = tid >> 2;
            const int l   = tid & 3;
            float vals[16];
            float m = -1e30f;
#pragma unroll
            for (int c = 0; c < 16; c++) {
                vals[c] = Ps[(l * 16 + c) * 65 + row];
                m = fmaxf(m, vals[c]);
            }
            m = fmaxf(m, __shfl_xor_sync(0xffffffffu, m, 1));
            m = fmaxf(m, __shfl_xor_sync(0xffffffffu, m, 2));
            const float mold = rowm[row];
            const float mnew = fmaxf(mold, m);
            float sum = 0.f;
#pragma unroll
            for (int c = 0; c < 16; c++) {
                float p = __expf(vals[c] - mnew);
                Ps[(l * 16 + c) * 65 + row] = p;
                sum += p;
            }
            sum += __shfl_xor_sync(0xffffffffu, sum, 1);
            sum += __shfl_xor_sync(0xffffffffu, sum, 2);
            if (l == 0) {
                float a = __expf(mold - mnew);
                rowa[row] = a;
                rowm[row] = mnew;
                rowl[row] = rowl[row] * a + sum;
            }
        }
        __syncthreads();

        float a[4];
#pragma unroll
        for (int i = 0; i < 4; i++) a[i] = rowa[rr * 4 + i];
#pragma unroll
        for (int i = 0; i < 4; i++)
#pragma unroll
            for (int j = 0; j < 4; j++) o[i][j] *= a[i];

#pragma unroll 8
        for (int n = 0; n < 64; n++) {
            float pv[4], vv[4];
#pragma unroll
            for (int i = 0; i < 4; i++) pv[i] = Ps[n * 65 + rr * 4 + i];
#pragma unroll
            for (int j = 0; j < 4; j++) vv[j] = Vs[n * 65 + cc * 4 + j];
#pragma unroll
            for (int i = 0; i < 4; i++)
#pragma unroll
                for (int j = 0; j < 4; j++)
                    o[i][j] = fmaf(pv[i], vv[j], o[i][j]);
        }
        __syncthreads();
    }

    float linv[4];
#pragma unroll
    for (int i = 0; i < 4; i++) linv[i] = 1.f / rowl[rr * 4 + i];
#pragma unroll
    for (int i = 0; i < 4; i++) {
        float* crow = C + base + (size_t)(qb * 64 + rr * 4 + i) * DMODEL + cc * 4;
#pragma unroll
        for (int j = 0; j < 4; j++)
            crow[j] = o[i][j] * linv[i];
    }
}

// ---------------------------------------------------------------------------
// Launch
// ---------------------------------------------------------------------------
extern "C" void kernel_launch(void* const* d_in, const int* in_sizes, int n_in,
                              void* d_out, int out_size)
{
    const float* X  = (const float*)d_in[0];
    const float* Wq = (const float*)d_in[1];
    const float* bq = (const float*)d_in[2];
    const float* Wk = (const float*)d_in[3];
    const float* bk = (const float*)d_in[4];
    const float* Wv = (const float*)d_in[5];
    const float* bv = (const float*)d_in[6];
    const float* Wo = (const float*)d_in[7];
    const float* bo = (const float*)d_in[8];
    float* out = (float*)d_out;

    float *Qp, *Kp, *Vp, *Cp;
    cudaGetSymbolAddress((void**)&Qp, g_Q);
    cudaGetSymbolAddress((void**)&Kp, g_K);
    cudaGetSymbolAddress((void**)&Vp, g_V);
    cudaGetSymbolAddress((void**)&Cp, g_C);

    static bool attr_set = false;
    if (!attr_set) {
        cudaFuncSetAttribute(attention_kernel,
                             cudaFuncAttributeMaxDynamicSharedMemorySize,
                             ATT_SMEM_FLOATS * (int)sizeof(float));
        attr_set = true;
    }

    dim3 gemm_grid(DMODEL / 128, MROWS / 128);   // (8, 128)
    gemm_tf32_nt<<<gemm_grid, 128>>>(X, Wq, bq, Qp, MROWS, DMODEL, DMODEL);
    gemm_tf32_nt<<<gemm_grid, 128>>>(X, Wk, bk, Kp, MROWS, DMODEL, DMODEL);
    gemm_tf32_nt<<<gemm_grid, 128>>>(X, Wv, bv, Vp, MROWS, DMODEL, DMODEL);

    dim3 att_grid(SEQ / 64, NHEAD, BATCH);       // (16, 16, 16)
    attention_kernel<<<att_grid, 256, ATT_SMEM_FLOATS * sizeof(float)>>>(Qp, Kp, Vp, Cp);

    gemm_tf32_nt<<<gemm_grid, 128>>>(Cp, Wo, bo, out, MROWS, DMODEL, DMODEL);
}

// round 4
// speedup vs baseline: 2.9332x; 1.7330x over previous
#include <cuda_runtime.h>
#include <cuda_bf16.h>
#include <cstdint>
#include <math.h>

// ---------------------------------------------------------------------------
// AttentionActPrune: full MHA block. B=16, S=1024, d=1024, H=16, Dh=64.
// Round 4: projection GEMMs (mma.sync tf32, unchanged) + NEW tensor-core
//          flash attention (m16n8k8 tf32, register softmax state).
// ---------------------------------------------------------------------------

#define BATCH   16
#define SEQ     1024
#define DMODEL  1024
#define NHEAD   16
#define DHEAD   64
#define MROWS   (BATCH * SEQ)          // 16384

__device__ float g_Q[(size_t)MROWS * DMODEL];
__device__ float g_K[(size_t)MROWS * DMODEL];
__device__ float g_V[(size_t)MROWS * DMODEL];
__device__ float g_C[(size_t)MROWS * DMODEL];

__device__ __forceinline__ uint32_t f2tf32(float f) {
    uint32_t u;
    asm("cvt.rna.tf32.f32 %0, %1;" : "=r"(u) : "f"(f));
    return u;
}

__device__ __forceinline__ void mma_tf32(float* c, uint32_t a0, uint32_t a1,
                                         uint32_t a2, uint32_t a3,
                                         uint32_t b0, uint32_t b1) {
    asm volatile(
        "mma.sync.aligned.m16n8k8.row.col.f32.tf32.tf32.f32 "
        "{%0,%1,%2,%3}, {%4,%5,%6,%7}, {%8,%9}, {%0,%1,%2,%3};"
        : "+f"(c[0]), "+f"(c[1]), "+f"(c[2]), "+f"(c[3])
        : "r"(a0), "r"(a1), "r"(a2), "r"(a3), "r"(b0), "r"(b1));
}

// ---------------------------------------------------------------------------
// tf32 GEMM (NT): C[m,n] = sum_k A[m,k]*B[n,k] + bias[n]   (unchanged R3)
// ---------------------------------------------------------------------------
#define GK 32
#define SSTRIDE 42

__global__ __launch_bounds__(128)
void gemm_tf32_nt(const float* __restrict__ A, const float* __restrict__ B,
                  const float* __restrict__ bias, float* __restrict__ C,
                  int M, int N, int K)
{
    __shared__ uint32_t sA[128 * SSTRIDE];
    __shared__ uint32_t sB[128 * SSTRIDE];

    const int tid  = threadIdx.x;
    const int wid  = tid >> 5;
    const int lane = tid & 31;
    const int g    = lane >> 2;
    const int tg   = lane & 3;

    const int warp_m = wid & 1;
    const int warp_n = wid >> 1;
    const int bm = blockIdx.y * 128;
    const int bn = blockIdx.x * 128;

    float acc[4][8][4];
#pragma unroll
    for (int i = 0; i < 4; i++)
#pragma unroll
        for (int j = 0; j < 8; j++)
#pragma unroll
            for (int q = 0; q < 4; q++) acc[i][j][q] = 0.f;

    for (int k0 = 0; k0 < K; k0 += GK) {
#pragma unroll
        for (int i = 0; i < 8; i++) {
            int idx = tid + i * 128;
            int r = idx >> 3;
            int c = idx & 7;
            int base = r * SSTRIDE + (c >> 1) * 8 + (c & 1);
            float4 va = *(const float4*)(A + (size_t)(bm + r) * K + k0 + c * 4);
            sA[base + 0] = f2tf32(va.x);
            sA[base + 2] = f2tf32(va.y);
            sA[base + 4] = f2tf32(va.z);
            sA[base + 6] = f2tf32(va.w);
            float4 vb = *(const float4*)(B + (size_t)(bn + r) * K + k0 + c * 4);
            sB[base + 0] = f2tf32(vb.x);
            sB[base + 2] = f2tf32(vb.y);
            sB[base + 4] = f2tf32(vb.z);
            sB[base + 6] = f2tf32(vb.w);
        }
        __syncthreads();

#pragma unroll
        for (int ks = 0; ks < 4; ks++) {
            const int kcol = ks * 8 + 2 * tg;
            uint2 aLo[4], aHi[4];
#pragma unroll
            for (int mt = 0; mt < 4; mt++) {
                int r = warp_m * 64 + mt * 16 + g;
                aLo[mt] = *(const uint2*)&sA[r * SSTRIDE + kcol];
                aHi[mt] = *(const uint2*)&sA[(r + 8) * SSTRIDE + kcol];
            }
            uint2 bf[8];
#pragma unroll
            for (int nt = 0; nt < 8; nt++) {
                int rn = warp_n * 64 + nt * 8 + g;
                bf[nt] = *(const uint2*)&sB[rn * SSTRIDE + kcol];
            }
#pragma unroll
            for (int mt = 0; mt < 4; mt++)
#pragma unroll
                for (int nt = 0; nt < 8; nt++)
                    mma_tf32(acc[mt][nt],
                             aLo[mt].x, aHi[mt].x, aLo[mt].y, aHi[mt].y,
                             bf[nt].x, bf[nt].y);
        }
        __syncthreads();
    }

#pragma unroll
    for (int mt = 0; mt < 4; mt++) {
        const int row0 = bm + warp_m * 64 + mt * 16 + g;
#pragma unroll
        for (int nt = 0; nt < 8; nt++) {
            const int col = bn + warp_n * 64 + nt * 8 + 2 * tg;
            const float b0 = bias[col], b1 = bias[col + 1];
            float2 v0 = make_float2(acc[mt][nt][0] + b0, acc[mt][nt][1] + b1);
            float2 v1 = make_float2(acc[mt][nt][2] + b0, acc[mt][nt][3] + b1);
            *(float2*)(C + (size_t)row0 * N + col) = v0;
            *(float2*)(C + (size_t)(row0 + 8) * N + col) = v1;
        }
    }
}

// ---------------------------------------------------------------------------
// Tensor-core flash attention.
// CTA = 128 q-rows of one (b,h). 4 warps x 32 rows. KB=64 keys/iter.
// Smem (uint32): Ps[128*66] (aliases Q staging), Ks[64*66], Vt[64*66].
// k-pair permutation within 8-groups: pos(k) = 2*(k&3) + (k>>2)  -> every
// fragment (k,k+4) is one 8B LDS.  Softmax state in registers (warp owns rows).
// ---------------------------------------------------------------------------
#define ASTR 66
#define ATT_SMEM_U32 (128 * ASTR + 64 * ASTR + 64 * ASTR)   // 16896 -> 66 KB

__global__ __launch_bounds__(128)
void attention_tc(const float* __restrict__ Q, const float* __restrict__ K,
                  const float* __restrict__ V, float* __restrict__ C)
{
    extern __shared__ uint32_t sm[];
    uint32_t* Ps = sm;                       // 128*ASTR (Q staging, then P)
    uint32_t* Ks = sm + 128 * ASTR;          // 64*ASTR
    uint32_t* Vt = Ks + 64 * ASTR;           // 64*ASTR (dh-major, key permuted)

    const int tid  = threadIdx.x;
    const int wid  = tid >> 5;
    const int lane = tid & 31;
    const int g    = lane >> 2;              // 0..7
    const int tg   = lane & 3;               // 0..3
    const int qb = blockIdx.x;               // 0..7  (128-row q block)
    const int h  = blockIdx.y;
    const int b  = blockIdx.z;
    const size_t base = (size_t)b * SEQ * DMODEL + (size_t)h * DHEAD;
    const int wr = wid * 32;                 // warp's first q row in tile

    // ---- stage Q (scaled by 1/8), tf32, k-permuted ----
#pragma unroll
    for (int i = 0; i < 16; i++) {
        int idx = tid + i * 128;             // 0..2047
        int r = idx >> 4, c = idx & 15;
        float4 v = *(const float4*)(Q + base + (size_t)(qb * 128 + r) * DMODEL + c * 4);
        int p0 = r * ASTR + (c >> 1) * 8 + (c & 1);
        Ps[p0 + 0] = f2tf32(v.x * 0.125f);
        Ps[p0 + 2] = f2tf32(v.y * 0.125f);
        Ps[p0 + 4] = f2tf32(v.z * 0.125f);
        Ps[p0 + 6] = f2tf32(v.w * 0.125f);
    }
    __syncthreads();

    // ---- hoist Q fragments to registers ----
    uint2 qLo[2][8], qHi[2][8];
#pragma unroll
    for (int mt = 0; mt < 2; mt++)
#pragma unroll
        for (int ks = 0; ks < 8; ks++) {
            qLo[mt][ks] = *(const uint2*)&Ps[(wr + mt * 16 + g) * ASTR + ks * 8 + 2 * tg];
            qHi[mt][ks] = *(const uint2*)&Ps[(wr + mt * 16 + g + 8) * ASTR + ks * 8 + 2 * tg];
        }
    __syncthreads();   // Ps free for P after this

    float o[2][8][4];
#pragma unroll
    for (int mt = 0; mt < 2; mt++)
#pragma unroll
        for (int nt = 0; nt < 8; nt++)
#pragma unroll
            for (int q = 0; q < 4; q++) o[mt][nt][q] = 0.f;
    float mst[2][2], lst[2][2];
#pragma unroll
    for (int mt = 0; mt < 2; mt++) {
        mst[mt][0] = mst[mt][1] = -1e30f;
        lst[mt][0] = lst[mt][1] = 0.f;
    }

    for (int kb = 0; kb < SEQ / 64; kb++) {
        // ---- stage K (key-major, dh-permuted) and V (dh-major, key-permuted) ----
#pragma unroll
        for (int i = 0; i < 8; i++) {
            int idx = tid + i * 128;         // 0..1023
            int key = idx >> 4, c = idx & 15;
            size_t gaddr = base + (size_t)(kb * 64 + key) * DMODEL + c * 4;
            float4 kv = *(const float4*)(K + gaddr);
            int p0 = key * ASTR + (c >> 1) * 8 + (c & 1);
            Ks[p0 + 0] = f2tf32(kv.x);
            Ks[p0 + 2] = f2tf32(kv.y);
            Ks[p0 + 4] = f2tf32(kv.z);
            Ks[p0 + 6] = f2tf32(kv.w);
            float4 vv = *(const float4*)(V + gaddr);
            int vp = (key & ~7) + 2 * (key & 3) + ((key >> 2) & 1);
            Vt[(c * 4 + 0) * ASTR + vp] = f2tf32(vv.x);
            Vt[(c * 4 + 1) * ASTR + vp] = f2tf32(vv.y);
            Vt[(c * 4 + 2) * ASTR + vp] = f2tf32(vv.z);
            Vt[(c * 4 + 3) * ASTR + vp] = f2tf32(vv.w);
        }
        __syncthreads();

        // ---- S = Q @ K^T  (warp: 32 q x 64 keys) ----
        float s[2][8][4];
#pragma unroll
        for (int mt = 0; mt < 2; mt++)
#pragma unroll
            for (int nt = 0; nt < 8; nt++)
#pragma unroll
                for (int q = 0; q < 4; q++) s[mt][nt][q] = 0.f;

#pragma unroll
        for (int ks = 0; ks < 8; ks++) {
            uint2 bf[8];
#pragma unroll
            for (int nt = 0; nt < 8; nt++)
                bf[nt] = *(const uint2*)&Ks[(nt * 8 + g) * ASTR + ks * 8 + 2 * tg];
#pragma unroll
            for (int mt = 0; mt < 2; mt++)
#pragma unroll
                for (int nt = 0; nt < 8; nt++)
                    mma_tf32(s[mt][nt],
                             qLo[mt][ks].x, qHi[mt][ks].x,
                             qLo[mt][ks].y, qHi[mt][ks].y,
                             bf[nt].x, bf[nt].y);
        }

        // ---- online softmax (state in registers; warp owns its rows) ----
#pragma unroll
        for (int mt = 0; mt < 2; mt++) {
            float mx0 = -1e30f, mx1 = -1e30f;
#pragma unroll
            for (int nt = 0; nt < 8; nt++) {
                mx0 = fmaxf(mx0, fmaxf(s[mt][nt][0], s[mt][nt][1]));
                mx1 = fmaxf(mx1, fmaxf(s[mt][nt][2], s[mt][nt][3]));
            }
            mx0 = fmaxf(mx0, __shfl_xor_sync(0xffffffffu, mx0, 1));
            mx0 = fmaxf(mx0, __shfl_xor_sync(0xffffffffu, mx0, 2));
            mx1 = fmaxf(mx1, __shfl_xor_sync(0xffffffffu, mx1, 1));
            mx1 = fmaxf(mx1, __shfl_xor_sync(0xffffffffu, mx1, 2));
            const float mn0 = fmaxf(mst[mt][0], mx0);
            const float mn1 = fmaxf(mst[mt][1], mx1);
            const float al0 = __expf(mst[mt][0] - mn0);
            const float al1 = __expf(mst[mt][1] - mn1);
            mst[mt][0] = mn0; mst[mt][1] = mn1;

            float sum0 = 0.f, sum1 = 0.f;
            const int r0 = (wr + mt * 16 + g) * ASTR;
            const int r1 = (wr + mt * 16 + g + 8) * ASTR;
#pragma unroll
            for (int nt = 0; nt < 8; nt++) {
#pragma unroll
                for (int c = 0; c < 2; c++) {
                    const int kk = 2 * tg + c;
                    const int pos = nt * 8 + 2 * (kk & 3) + (kk >> 2);
                    float p0 = __expf(s[mt][nt][c]     - mn0);
                    float p1 = __expf(s[mt][nt][2 + c] - mn1);
                    sum0 += p0; sum1 += p1;
                    Ps[r0 + pos] = f2tf32(p0);
                    Ps[r1 + pos] = f2tf32(p1);
                }
                o[mt][nt][0] *= al0; o[mt][nt][1] *= al0;
                o[mt][nt][2] *= al1; o[mt][nt][3] *= al1;
            }
            sum0 += __shfl_xor_sync(0xffffffffu, sum0, 1);
            sum0 += __shfl_xor_sync(0xffffffffu, sum0, 2);
            sum1 += __shfl_xor_sync(0xffffffffu, sum1, 1);
            sum1 += __shfl_xor_sync(0xffffffffu, sum1, 2);
            lst[mt][0] = lst[mt][0] * al0 + sum0;
            lst[mt][1] = lst[mt][1] * al1 + sum1;
        }
        __syncwarp();   // P writes visible to the warp's own fragment loads

        // ---- O += P @ V  (k = 64 keys) ----
#pragma unroll
        for (int ks = 0; ks < 8; ks++) {
            uint2 bf[8];
#pragma unroll
            for (int nt = 0; nt < 8; nt++)
                bf[nt] = *(const uint2*)&Vt[(nt * 8 + g) * ASTR + ks * 8 + 2 * tg];
            uint2 aLo[2], aHi[2];
#pragma unroll
            for (int mt = 0; mt < 2; mt++) {
                aLo[mt] = *(const uint2*)&Ps[(wr + mt * 16 + g) * ASTR + ks * 8 + 2 * tg];
                aHi[mt] = *(const uint2*)&Ps[(wr + mt * 16 + g + 8) * ASTR + ks * 8 + 2 * tg];
            }
#pragma unroll
            for (int mt = 0; mt < 2; mt++)
#pragma unroll
                for (int nt = 0; nt < 8; nt++)
                    mma_tf32(o[mt][nt],
                             aLo[mt].x, aHi[mt].x, aLo[mt].y, aHi[mt].y,
                             bf[nt].x, bf[nt].y);
        }
        __syncthreads();   // Ks/Vt/Ps consumed before restaging
    }

    // ---- normalize + store ctx in [b, s, h*64+dh] layout ----
#pragma unroll
    for (int mt = 0; mt < 2; mt++) {
        const float li0 = 1.f / lst[mt][0];
        const float li1 = 1.f / lst[mt][1];
        const size_t r0 = base + (size_t)(qb * 128 + wr + mt * 16 + g) * DMODEL;
        const size_t r1 = r0 + (size_t)8 * DMODEL;
#pragma unroll
        for (int nt = 0; nt < 8; nt++) {
            const int col = nt * 8 + 2 * tg;
            *(float2*)(C + r0 + col) = make_float2(o[mt][nt][0] * li0, o[mt][nt][1] * li0);
            *(float2*)(C + r1 + col) = make_float2(o[mt][nt][2] * li1, o[mt][nt][3] * li1);
        }
    }
}

// ---------------------------------------------------------------------------
// Launch
// ---------------------------------------------------------------------------
extern "C" void kernel_launch(void* const* d_in, const int* in_sizes, int n_in,
                              void* d_out, int out_size)
{
    const float* X  = (const float*)d_in[0];
    const float* Wq = (const float*)d_in[1];
    const float* bq = (const float*)d_in[2];
    const float* Wk = (const float*)d_in[3];
    const float* bk = (const float*)d_in[4];
    const float* Wv = (const float*)d_in[5];
    const float* bv = (const float*)d_in[6];
    const float* Wo = (const float*)d_in[7];
    const float* bo = (const float*)d_in[8];
    float* out = (float*)d_out;

    float *Qp, *Kp, *Vp, *Cp;
    cudaGetSymbolAddress((void**)&Qp, g_Q);
    cudaGetSymbolAddress((void**)&Kp, g_K);
    cudaGetSymbolAddress((void**)&Vp, g_V);
    cudaGetSymbolAddress((void**)&Cp, g_C);

    static bool attr_set = false;
    if (!attr_set) {
        cudaFuncSetAttribute(attention_tc,
                             cudaFuncAttributeMaxDynamicSharedMemorySize,
                             ATT_SMEM_U32 * (int)sizeof(uint32_t));
        attr_set = true;
    }

    dim3 gemm_grid(DMODEL / 128, MROWS / 128);   // (8, 128)
    gemm_tf32_nt<<<gemm_grid, 128>>>(X, Wq, bq, Qp, MROWS, DMODEL, DMODEL);
    gemm_tf32_nt<<<gemm_grid, 128>>>(X, Wk, bk, Kp, MROWS, DMODEL, DMODEL);
    gemm_tf32_nt<<<gemm_grid, 128>>>(X, Wv, bv, Vp, MROWS, DMODEL, DMODEL);

    dim3 att_grid(SEQ / 128, NHEAD, BATCH);      // (8, 16, 16)
    attention_tc<<<att_grid, 128, ATT_SMEM_U32 * sizeof(uint32_t)>>>(Qp, Kp, Vp, Cp);

    gemm_tf32_nt<<<gemm_grid, 128>>>(Cp, Wo, bo, out, MROWS, DMODEL, DMODEL);
}

// round 5
// speedup vs baseline: 3.0615x; 1.0437x over previous
#include <cuda_runtime.h>
#include <cuda_bf16.h>
#include <cstdint>
#include <math.h>

// ---------------------------------------------------------------------------
// AttentionActPrune: full MHA block. B=16, S=1024, d=1024, H=16, Dh=64.
// Round 5: attention smem bank-conflict fix (ASTR 66->74), key-pair V staging
//          (STS.64), 256-thread CTA with 16 rows/warp. GEMM unchanged.
// ---------------------------------------------------------------------------

#define BATCH   16
#define SEQ     1024
#define DMODEL  1024
#define NHEAD   16
#define DHEAD   64
#define MROWS   (BATCH * SEQ)          // 16384

__device__ float g_Q[(size_t)MROWS * DMODEL];
__device__ float g_K[(size_t)MROWS * DMODEL];
__device__ float g_V[(size_t)MROWS * DMODEL];
__device__ float g_C[(size_t)MROWS * DMODEL];

__device__ __forceinline__ uint32_t f2tf32(float f) {
    uint32_t u;
    asm("cvt.rna.tf32.f32 %0, %1;" : "=r"(u) : "f"(f));
    return u;
}

__device__ __forceinline__ void mma_tf32(float* c, uint32_t a0, uint32_t a1,
                                         uint32_t a2, uint32_t a3,
                                         uint32_t b0, uint32_t b1) {
    asm volatile(
        "mma.sync.aligned.m16n8k8.row.col.f32.tf32.tf32.f32 "
        "{%0,%1,%2,%3}, {%4,%5,%6,%7}, {%8,%9}, {%0,%1,%2,%3};"
        : "+f"(c[0]), "+f"(c[1]), "+f"(c[2]), "+f"(c[3])
        : "r"(a0), "r"(a1), "r"(a2), "r"(a3), "r"(b0), "r"(b1));
}

// ---------------------------------------------------------------------------
// tf32 GEMM (NT): C[m,n] = sum_k A[m,k]*B[n,k] + bias[n]   (unchanged R3)
// ---------------------------------------------------------------------------
#define GK 32
#define SSTRIDE 42

__global__ __launch_bounds__(128)
void gemm_tf32_nt(const float* __restrict__ A, const float* __restrict__ B,
                  const float* __restrict__ bias, float* __restrict__ C,
                  int M, int N, int K)
{
    __shared__ uint32_t sA[128 * SSTRIDE];
    __shared__ uint32_t sB[128 * SSTRIDE];

    const int tid  = threadIdx.x;
    const int wid  = tid >> 5;
    const int lane = tid & 31;
    const int g    = lane >> 2;
    const int tg   = lane & 3;

    const int warp_m = wid & 1;
    const int warp_n = wid >> 1;
    const int bm = blockIdx.y * 128;
    const int bn = blockIdx.x * 128;

    float acc[4][8][4];
#pragma unroll
    for (int i = 0; i < 4; i++)
#pragma unroll
        for (int j = 0; j < 8; j++)
#pragma unroll
            for (int q = 0; q < 4; q++) acc[i][j][q] = 0.f;

    for (int k0 = 0; k0 < K; k0 += GK) {
#pragma unroll
        for (int i = 0; i < 8; i++) {
            int idx = tid + i * 128;
            int r = idx >> 3;
            int c = idx & 7;
            int base = r * SSTRIDE + (c >> 1) * 8 + (c & 1);
            float4 va = *(const float4*)(A + (size_t)(bm + r) * K + k0 + c * 4);
            sA[base + 0] = f2tf32(va.x);
            sA[base + 2] = f2tf32(va.y);
            sA[base + 4] = f2tf32(va.z);
            sA[base + 6] = f2tf32(va.w);
            float4 vb = *(const float4*)(B + (size_t)(bn + r) * K + k0 + c * 4);
            sB[base + 0] = f2tf32(vb.x);
            sB[base + 2] = f2tf32(vb.y);
            sB[base + 4] = f2tf32(vb.z);
            sB[base + 6] = f2tf32(vb.w);
        }
        __syncthreads();

#pragma unroll
        for (int ks = 0; ks < 4; ks++) {
            const int kcol = ks * 8 + 2 * tg;
            uint2 aLo[4], aHi[4];
#pragma unroll
            for (int mt = 0; mt < 4; mt++) {
                int r = warp_m * 64 + mt * 16 + g;
                aLo[mt] = *(const uint2*)&sA[r * SSTRIDE + kcol];
                aHi[mt] = *(const uint2*)&sA[(r + 8) * SSTRIDE + kcol];
            }
            uint2 bf[8];
#pragma unroll
            for (int nt = 0; nt < 8; nt++) {
                int rn = warp_n * 64 + nt * 8 + g;
                bf[nt] = *(const uint2*)&sB[rn * SSTRIDE + kcol];
            }
#pragma unroll
            for (int mt = 0; mt < 4; mt++)
#pragma unroll
                for (int nt = 0; nt < 8; nt++)
                    mma_tf32(acc[mt][nt],
                             aLo[mt].x, aHi[mt].x, aLo[mt].y, aHi[mt].y,
                             bf[nt].x, bf[nt].y);
        }
        __syncthreads();
    }

#pragma unroll
    for (int mt = 0; mt < 4; mt++) {
        const int row0 = bm + warp_m * 64 + mt * 16 + g;
#pragma unroll
        for (int nt = 0; nt < 8; nt++) {
            const int col = bn + warp_n * 64 + nt * 8 + 2 * tg;
            const float b0 = bias[col], b1 = bias[col + 1];
            float2 v0 = make_float2(acc[mt][nt][0] + b0, acc[mt][nt][1] + b1);
            float2 v1 = make_float2(acc[mt][nt][2] + b0, acc[mt][nt][3] + b1);
            *(float2*)(C + (size_t)row0 * N + col) = v0;
            *(float2*)(C + (size_t)(row0 + 8) * N + col) = v1;
        }
    }
}

// ---------------------------------------------------------------------------
// Tensor-core flash attention (round 5).
// CTA = 128 q-rows of one (b,h). 8 warps x 16 rows. KB=64 keys/iter.
// ASTR=74: fragment LDS bank pattern (10g+2tg)%32 -> near conflict-free.
// V staged via key-pairs: one STS.64 per (d, pair) -> no column scatter.
// ---------------------------------------------------------------------------
#define ASTR 74
#define ATT_SMEM_U32 (128 * ASTR + 64 * ASTR + 64 * ASTR)   // 18944 u32 = 74 KB

__global__ __launch_bounds__(256, 2)
void attention_tc(const float* __restrict__ Q, const float* __restrict__ K,
                  const float* __restrict__ V, float* __restrict__ C)
{
    extern __shared__ uint32_t sm[];
    uint32_t* Ps = sm;                       // 128*ASTR (Q staging, then P)
    uint32_t* Ks = sm + 128 * ASTR;          // 64*ASTR (key-major, k-permuted)
    uint32_t* Vt = Ks + 64 * ASTR;           // 64*ASTR (d-major, key-permuted)

    const int tid  = threadIdx.x;
    const int wid  = tid >> 5;               // 0..7
    const int lane = tid & 31;
    const int g    = lane >> 2;              // 0..7
    const int tg   = lane & 3;               // 0..3
    const int qb = blockIdx.x;               // 0..7
    const int h  = blockIdx.y;
    const int b  = blockIdx.z;
    const size_t base = (size_t)b * SEQ * DMODEL + (size_t)h * DHEAD;
    const int wr = wid * 16;                 // warp's first q row

    // ---- stage Q (scaled 1/8), tf32, k-pair permuted ----
#pragma unroll
    for (int i = 0; i < 8; i++) {
        int idx = tid + i * 256;             // 0..2047
        int r = idx >> 4, c = idx & 15;
        float4 v = *(const float4*)(Q + base + (size_t)(qb * 128 + r) * DMODEL + c * 4);
        int p0 = r * ASTR + (c >> 1) * 8 + (c & 1);
        Ps[p0 + 0] = f2tf32(v.x * 0.125f);
        Ps[p0 + 2] = f2tf32(v.y * 0.125f);
        Ps[p0 + 4] = f2tf32(v.z * 0.125f);
        Ps[p0 + 6] = f2tf32(v.w * 0.125f);
    }
    __syncthreads();

    // ---- hoist Q fragments (16 rows/warp) ----
    uint2 qLo[8], qHi[8];
#pragma unroll
    for (int ks = 0; ks < 8; ks++) {
        qLo[ks] = *(const uint2*)&Ps[(wr + g) * ASTR + ks * 8 + 2 * tg];
        qHi[ks] = *(const uint2*)&Ps[(wr + g + 8) * ASTR + ks * 8 + 2 * tg];
    }
    __syncthreads();   // Ps free for P after this

    float o[8][4];
#pragma unroll
    for (int nt = 0; nt < 8; nt++)
#pragma unroll
        for (int q = 0; q < 4; q++) o[nt][q] = 0.f;
    float m0 = -1e30f, m1 = -1e30f, l0 = 0.f, l1 = 0.f;

    for (int kb = 0; kb < SEQ / 64; kb++) {
        // ---- stage K: key-major, dh-permuted (conflict-free STS.32) ----
#pragma unroll
        for (int i = 0; i < 4; i++) {
            int idx = tid + i * 256;         // 0..1023
            int key = idx >> 4, c = idx & 15;
            float4 kv = *(const float4*)(K + base + (size_t)(kb * 64 + key) * DMODEL + c * 4);
            int p0 = key * ASTR + (c >> 1) * 8 + (c & 1);
            Ks[p0 + 0] = f2tf32(kv.x);
            Ks[p0 + 2] = f2tf32(kv.y);
            Ks[p0 + 4] = f2tf32(kv.z);
            Ks[p0 + 6] = f2tf32(kv.w);
        }
        // ---- stage V transposed via key-pairs: one STS.64 per task ----
#pragma unroll
        for (int i = 0; i < 8; i++) {
            int idx = tid + i * 256;         // 0..2047
            int d   = idx & 63;
            int pid = idx >> 6;              // 0..31
            int gg  = pid >> 2, pp = pid & 3;
            const float* vp = V + base + (size_t)(kb * 64 + gg * 8 + pp) * DMODEL + d;
            float v1 = vp[0];
            float v2 = vp[(size_t)4 * DMODEL];
            uint2 pkt = make_uint2(f2tf32(v1), f2tf32(v2));
            *(uint2*)&Vt[d * ASTR + gg * 8 + 2 * pp] = pkt;
        }
        __syncthreads();

        // ---- S = Q @ K^T  (warp: 16 q x 64 keys) ----
        float s[8][4];
#pragma unroll
        for (int nt = 0; nt < 8; nt++)
#pragma unroll
            for (int q = 0; q < 4; q++) s[nt][q] = 0.f;

#pragma unroll
        for (int ks = 0; ks < 8; ks++) {
#pragma unroll
            for (int nt = 0; nt < 8; nt++) {
                uint2 bf = *(const uint2*)&Ks[(nt * 8 + g) * ASTR + ks * 8 + 2 * tg];
                mma_tf32(s[nt], qLo[ks].x, qHi[ks].x, qLo[ks].y, qHi[ks].y,
                         bf.x, bf.y);
            }
        }

        // ---- online softmax (register state; warp owns its rows) ----
        {
            float mx0 = -1e30f, mx1 = -1e30f;
#pragma unroll
            for (int nt = 0; nt < 8; nt++) {
                mx0 = fmaxf(mx0, fmaxf(s[nt][0], s[nt][1]));
                mx1 = fmaxf(mx1, fmaxf(s[nt][2], s[nt][3]));
            }
            mx0 = fmaxf(mx0, __shfl_xor_sync(0xffffffffu, mx0, 1));
            mx0 = fmaxf(mx0, __shfl_xor_sync(0xffffffffu, mx0, 2));
            mx1 = fmaxf(mx1, __shfl_xor_sync(0xffffffffu, mx1, 1));
            mx1 = fmaxf(mx1, __shfl_xor_sync(0xffffffffu, mx1, 2));
            const float mn0 = fmaxf(m0, mx0);
            const float mn1 = fmaxf(m1, mx1);
            const float al0 = __expf(m0 - mn0);
            const float al1 = __expf(m1 - mn1);
            m0 = mn0; m1 = mn1;

            float sum0 = 0.f, sum1 = 0.f;
            const int r0 = (wr + g) * ASTR;
            const int r1 = (wr + g + 8) * ASTR;
#pragma unroll
            for (int nt = 0; nt < 8; nt++) {
#pragma unroll
                for (int c = 0; c < 2; c++) {
                    const int kk = 2 * tg + c;
                    const int pos = nt * 8 + 2 * (kk & 3) + (kk >> 2);
                    float p0 = __expf(s[nt][c]     - mn0);
                    float p1 = __expf(s[nt][2 + c] - mn1);
                    sum0 += p0; sum1 += p1;
                    Ps[r0 + pos] = f2tf32(p0);
                    Ps[r1 + pos] = f2tf32(p1);
                }
                o[nt][0] *= al0; o[nt][1] *= al0;
                o[nt][2] *= al1; o[nt][3] *= al1;
            }
            sum0 += __shfl_xor_sync(0xffffffffu, sum0, 1);
            sum0 += __shfl_xor_sync(0xffffffffu, sum0, 2);
            sum1 += __shfl_xor_sync(0xffffffffu, sum1, 1);
            sum1 += __shfl_xor_sync(0xffffffffu, sum1, 2);
            l0 = l0 * al0 + sum0;
            l1 = l1 * al1 + sum1;
        }
        __syncwarp();   // P visible to this warp's fragment loads

        // ---- O += P @ V ----
#pragma unroll
        for (int ks = 0; ks < 8; ks++) {
            uint2 aLo = *(const uint2*)&Ps[(wr + g) * ASTR + ks * 8 + 2 * tg];
            uint2 aHi = *(const uint2*)&Ps[(wr + g + 8) * ASTR + ks * 8 + 2 * tg];
#pragma unroll
            for (int nt = 0; nt < 8; nt++) {
                uint2 bf = *(const uint2*)&Vt[(nt * 8 + g) * ASTR + ks * 8 + 2 * tg];
                mma_tf32(o[nt], aLo.x, aHi.x, aLo.y, aHi.y, bf.x, bf.y);
            }
        }
        __syncthreads();   // Ks/Vt consumed before restaging
    }

    // ---- normalize + store ctx in [b, s, h*64+dh] layout ----
    {
        const float li0 = 1.f / l0;
        const float li1 = 1.f / l1;
        const size_t r0 = base + (size_t)(qb * 128 + wr + g) * DMODEL;
        const size_t r1 = r0 + (size_t)8 * DMODEL;
#pragma unroll
        for (int nt = 0; nt < 8; nt++) {
            const int col = nt * 8 + 2 * tg;
            *(float2*)(C + r0 + col) = make_float2(o[nt][0] * li0, o[nt][1] * li0);
            *(float2*)(C + r1 + col) = make_float2(o[nt][2] * li1, o[nt][3] * li1);
        }
    }
}

// ---------------------------------------------------------------------------
// Launch
// ---------------------------------------------------------------------------
extern "C" void kernel_launch(void* const* d_in, const int* in_sizes, int n_in,
                              void* d_out, int out_size)
{
    const float* X  = (const float*)d_in[0];
    const float* Wq = (const float*)d_in[1];
    const float* bq = (const float*)d_in[2];
    const float* Wk = (const float*)d_in[3];
    const float* bk = (const float*)d_in[4];
    const float* Wv = (const float*)d_in[5];
    const float* bv = (const float*)d_in[6];
    const float* Wo = (const float*)d_in[7];
    const float* bo = (const float*)d_in[8];
    float* out = (float*)d_out;

    float *Qp, *Kp, *Vp, *Cp;
    cudaGetSymbolAddress((void**)&Qp, g_Q);
    cudaGetSymbolAddress((void**)&Kp, g_K);
    cudaGetSymbolAddress((void**)&Vp, g_V);
    cudaGetSymbolAddress((void**)&Cp, g_C);

    static bool attr_set = false;
    if (!attr_set) {
        cudaFuncSetAttribute(attention_tc,
                             cudaFuncAttributeMaxDynamicSharedMemorySize,
                             ATT_SMEM_U32 * (int)sizeof(uint32_t));
        attr_set = true;
    }

    dim3 gemm_grid(DMODEL / 128, MROWS / 128);   // (8, 128)
    gemm_tf32_nt<<<gemm_grid, 128>>>(X, Wq, bq, Qp, MROWS, DMODEL, DMODEL);
    gemm_tf32_nt<<<gemm_grid, 128>>>(X, Wk, bk, Kp, MROWS, DMODEL, DMODEL);
    gemm_tf32_nt<<<gemm_grid, 128>>>(X, Wv, bv, Vp, MROWS, DMODEL, DMODEL);

    dim3 att_grid(SEQ / 128, NHEAD, BATCH);      // (8, 16, 16)
    attention_tc<<<att_grid, 256, ATT_SMEM_U32 * sizeof(uint32_t)>>>(Qp, Kp, Vp, Cp);

    gemm_tf32_nt<<<gemm_grid, 128>>>(Cp, Wo, bo, out, MROWS, DMODEL, DMODEL);
}

// round 7
// speedup vs baseline: 3.1974x; 1.0444x over previous
#include <cuda_runtime.h>
#include <cuda_fp16.h>
#include <cstdint>
#include <math.h>

// ---------------------------------------------------------------------------
// AttentionActPrune: full MHA block. B=16, S=1024, d=1024, H=16, Dh=64.
// Round 7: R6 with the VSTR alignment fix (41 -> 42; uint2 loads need even
//          u32 stride). Attention: fp16 m16n8k16 PV, register-resident P.
//          GEMM: register-prefetch double buffering.
// ---------------------------------------------------------------------------

#define BATCH   16
#define SEQ     1024
#define DMODEL  1024
#define NHEAD   16
#define DHEAD   64
#define MROWS   (BATCH * SEQ)          // 16384

__device__ float g_Q[(size_t)MROWS * DMODEL];
__device__ float g_K[(size_t)MROWS * DMODEL];
__device__ float g_V[(size_t)MROWS * DMODEL];
__device__ float g_C[(size_t)MROWS * DMODEL];

__device__ __forceinline__ uint32_t f2tf32(float f) {
    uint32_t u;
    asm("cvt.rna.tf32.f32 %0, %1;" : "=r"(u) : "f"(f));
    return u;
}

__device__ __forceinline__ void mma_tf32(float* c, uint32_t a0, uint32_t a1,
                                         uint32_t a2, uint32_t a3,
                                         uint32_t b0, uint32_t b1) {
    asm volatile(
        "mma.sync.aligned.m16n8k8.row.col.f32.tf32.tf32.f32 "
        "{%0,%1,%2,%3}, {%4,%5,%6,%7}, {%8,%9}, {%0,%1,%2,%3};"
        : "+f"(c[0]), "+f"(c[1]), "+f"(c[2]), "+f"(c[3])
        : "r"(a0), "r"(a1), "r"(a2), "r"(a3), "r"(b0), "r"(b1));
}

__device__ __forceinline__ void mma_fp16(float* c, uint32_t a0, uint32_t a1,
                                         uint32_t a2, uint32_t a3,
                                         uint32_t b0, uint32_t b1) {
    asm volatile(
        "mma.sync.aligned.m16n8k16.row.col.f32.f16.f16.f32 "
        "{%0,%1,%2,%3}, {%4,%5,%6,%7}, {%8,%9}, {%0,%1,%2,%3};"
        : "+f"(c[0]), "+f"(c[1]), "+f"(c[2]), "+f"(c[3])
        : "r"(a0), "r"(a1), "r"(a2), "r"(a3), "r"(b0), "r"(b1));
}

__device__ __forceinline__ uint32_t pack_h2(float lo, float hi) {
    __half2 h = __floats2half2_rn(lo, hi);
    return *(uint32_t*)&h;
}

// ---------------------------------------------------------------------------
// tf32 GEMM (NT), double-buffered: C[m,n] = sum_k A[m,k]*B[n,k] + bias[n]
// 256 threads, 8 warps (2 x 4), warp tile 64x32 (mt=4, nt=4). BK=32.
// Register prefetch of tile k+1 overlaps MMA of tile k; 2 smem buffers,
// one barrier per iteration (barrier between STS and MMA makes this safe).
// ---------------------------------------------------------------------------
#define SSTRIDE 42
#define GEMM_BUF (128 * SSTRIDE)                  // u32 per tile buffer
#define GEMM_SMEM_U32 (4 * GEMM_BUF)              // 2 x (A,B) = 86 KB

__global__ __launch_bounds__(256)
void gemm_tf32_nt(const float* __restrict__ A, const float* __restrict__ B,
                  const float* __restrict__ bias, float* __restrict__ C,
                  int M, int N, int K)
{
    extern __shared__ uint32_t gsm[];
    uint32_t* sA = gsm;                  // [2][GEMM_BUF]
    uint32_t* sB = gsm + 2 * GEMM_BUF;   // [2][GEMM_BUF]

    const int tid  = threadIdx.x;
    const int wid  = tid >> 5;
    const int lane = tid & 31;
    const int g    = lane >> 2;
    const int tg   = lane & 3;
    const int warp_m = wid & 1;          // 2 warps along M
    const int warp_n = wid >> 1;         // 4 warps along N
    const int bm = blockIdx.y * 128;
    const int bn = blockIdx.x * 128;

    float4 pa[4], pb[4];
#pragma unroll
    for (int i = 0; i < 4; i++) {
        int idx = tid + i * 256;
        int r = idx >> 3, c = idx & 7;
        pa[i] = *(const float4*)(A + (size_t)(bm + r) * K + c * 4);
        pb[i] = *(const float4*)(B + (size_t)(bn + r) * K + c * 4);
    }

    float acc[4][4][4];
#pragma unroll
    for (int i = 0; i < 4; i++)
#pragma unroll
        for (int j = 0; j < 4; j++)
#pragma unroll
            for (int q = 0; q < 4; q++) acc[i][j][q] = 0.f;

    const int nkc = K / 32;
    for (int kc = 0; kc < nkc; kc++) {
        uint32_t* bufA = sA + (kc & 1) * GEMM_BUF;
        uint32_t* bufB = sB + (kc & 1) * GEMM_BUF;
#pragma unroll
        for (int i = 0; i < 4; i++) {
            int idx = tid + i * 256;
            int r = idx >> 3, c = idx & 7;
            int base = r * SSTRIDE + (c >> 1) * 8 + (c & 1);
            bufA[base + 0] = f2tf32(pa[i].x);
            bufA[base + 2] = f2tf32(pa[i].y);
            bufA[base + 4] = f2tf32(pa[i].z);
            bufA[base + 6] = f2tf32(pa[i].w);
            bufB[base + 0] = f2tf32(pb[i].x);
            bufB[base + 2] = f2tf32(pb[i].y);
            bufB[base + 4] = f2tf32(pb[i].z);
            bufB[base + 6] = f2tf32(pb[i].w);
        }
        __syncthreads();

        if (kc + 1 < nkc) {
            const int k0n = (kc + 1) * 32;
#pragma unroll
            for (int i = 0; i < 4; i++) {
                int idx = tid + i * 256;
                int r = idx >> 3, c = idx & 7;
                pa[i] = *(const float4*)(A + (size_t)(bm + r) * K + k0n + c * 4);
                pb[i] = *(const float4*)(B + (size_t)(bn + r) * K + k0n + c * 4);
            }
        }

#pragma unroll
        for (int ks = 0; ks < 4; ks++) {
            const int kcol = ks * 8 + 2 * tg;
            uint2 aLo[4], aHi[4];
#pragma unroll
            for (int mt = 0; mt < 4; mt++) {
                int r = warp_m * 64 + mt * 16 + g;
                aLo[mt] = *(const uint2*)&bufA[r * SSTRIDE + kcol];
                aHi[mt] = *(const uint2*)&bufA[(r + 8) * SSTRIDE + kcol];
            }
            uint2 bf[4];
#pragma unroll
            for (int nt = 0; nt < 4; nt++) {
                int rn = warp_n * 32 + nt * 8 + g;
                bf[nt] = *(const uint2*)&bufB[rn * SSTRIDE + kcol];
            }
#pragma unroll
            for (int mt = 0; mt < 4; mt++)
#pragma unroll
                for (int nt = 0; nt < 4; nt++)
                    mma_tf32(acc[mt][nt],
                             aLo[mt].x, aHi[mt].x, aLo[mt].y, aHi[mt].y,
                             bf[nt].x, bf[nt].y);
        }
        // no trailing barrier: next iteration writes the OTHER buffer;
        // the barrier above (between STS and MMA) provides the ordering.
    }

#pragma unroll
    for (int mt = 0; mt < 4; mt++) {
        const int row0 = bm + warp_m * 64 + mt * 16 + g;
#pragma unroll
        for (int nt = 0; nt < 4; nt++) {
            const int col = bn + warp_n * 32 + nt * 8 + 2 * tg;
            const float b0 = bias[col], b1 = bias[col + 1];
            float2 v0 = make_float2(acc[mt][nt][0] + b0, acc[mt][nt][1] + b1);
            float2 v1 = make_float2(acc[mt][nt][2] + b0, acc[mt][nt][3] + b1);
            *(float2*)(C + (size_t)row0 * N + col) = v0;
            *(float2*)(C + (size_t)(row0 + 8) * N + col) = v1;
        }
    }
}

// ---------------------------------------------------------------------------
// Tensor-core flash attention (round 7).
// CTA = 128 q-rows, 128 threads, 4 warps x 32 rows (mt=2). KB=64 keys/iter.
// QK: tf32 m16n8k8 (Q,K smem, ASTR=74). PV: fp16 m16n8k16, P in registers
// (accumulator layout == A-fragment layout), V as half2 key-pairs, VSTR=42
// (EVEN: uint2 fragment loads stay 8B-aligned).
// ---------------------------------------------------------------------------
#define ASTR 74
#define VSTR 42
#define Q_U32 (128 * ASTR)
#define K_U32 (64 * ASTR)
#define V_U32 (64 * VSTR)
#define ATT_SMEM_U32 (Q_U32 + K_U32 + V_U32)   // 16896 u32 = 67584 B

__global__ __launch_bounds__(128, 2)
void attention_tc(const float* __restrict__ Q, const float* __restrict__ K,
                  const float* __restrict__ V, float* __restrict__ C)
{
    extern __shared__ uint32_t sm[];
    uint32_t* Qs = sm;                   // tf32, k-pair permuted
    uint32_t* Ks = sm + Q_U32;           // tf32, k-pair permuted
    uint32_t* Vt = Ks + K_U32;           // half2 (key,key+1), d-major, kp-permuted

    const int tid  = threadIdx.x;
    const int wid  = tid >> 5;           // 0..3
    const int lane = tid & 31;
    const int g    = lane >> 2;          // 0..7
    const int tg   = lane & 3;           // 0..3
    const int qb = blockIdx.x;           // 0..7
    const int h  = blockIdx.y;
    const int b  = blockIdx.z;
    const size_t base = (size_t)b * SEQ * DMODEL + (size_t)h * DHEAD;
    const int wr = wid * 32;             // warp's first q row (32 rows/warp)

    // ---- stage Q (scaled 1/8), tf32, k-pair permuted ----
#pragma unroll
    for (int i = 0; i < 16; i++) {
        int idx = tid + i * 128;         // 0..2047
        int r = idx >> 4, c = idx & 15;
        float4 v = *(const float4*)(Q + base + (size_t)(qb * 128 + r) * DMODEL + c * 4);
        int p0 = r * ASTR + (c >> 1) * 8 + (c & 1);
        Qs[p0 + 0] = f2tf32(v.x * 0.125f);
        Qs[p0 + 2] = f2tf32(v.y * 0.125f);
        Qs[p0 + 4] = f2tf32(v.z * 0.125f);
        Qs[p0 + 6] = f2tf32(v.w * 0.125f);
    }
    __syncthreads();

    float o[2][8][4];
#pragma unroll
    for (int mt = 0; mt < 2; mt++)
#pragma unroll
        for (int nt = 0; nt < 8; nt++)
#pragma unroll
            for (int q = 0; q < 4; q++) o[mt][nt][q] = 0.f;
    float mrow[2][2], lrow[2][2];
#pragma unroll
    for (int mt = 0; mt < 2; mt++) {
        mrow[mt][0] = mrow[mt][1] = -1e30f;
        lrow[mt][0] = lrow[mt][1] = 0.f;
    }

    for (int kb = 0; kb < SEQ / 64; kb++) {
        // ---- stage K: tf32, key-major, k-pair permuted ----
#pragma unroll
        for (int i = 0; i < 8; i++) {
            int idx = tid + i * 128;     // 0..1023
            int key = idx >> 4, c = idx & 15;
            float4 kv = *(const float4*)(K + base + (size_t)(kb * 64 + key) * DMODEL + c * 4);
            int p0 = key * ASTR + (c >> 1) * 8 + (c & 1);
            Ks[p0 + 0] = f2tf32(kv.x);
            Ks[p0 + 2] = f2tf32(kv.y);
            Ks[p0 + 4] = f2tf32(kv.z);
            Ks[p0 + 6] = f2tf32(kv.w);
        }
        // ---- stage V: half2 key-pairs, d-major, pair-permuted in 8-groups ----
#pragma unroll
        for (int i = 0; i < 4; i++) {
            int t = tid + i * 128;       // 0..511
            int p  = t >> 4;             // key pair 0..31 (keys 2p, 2p+1)
            int dc = t & 15;             // d float4-chunk
            const float* vb = V + base + (size_t)(kb * 64 + 2 * p) * DMODEL + dc * 4;
            float4 v0 = *(const float4*)(vb);
            float4 v1 = *(const float4*)(vb + DMODEL);
            int pos = (p & ~7) + 2 * (p & 3) + ((p >> 2) & 1);
            Vt[(dc * 4 + 0) * VSTR + pos] = pack_h2(v0.x, v1.x);
            Vt[(dc * 4 + 1) * VSTR + pos] = pack_h2(v0.y, v1.y);
            Vt[(dc * 4 + 2) * VSTR + pos] = pack_h2(v0.z, v1.z);
            Vt[(dc * 4 + 3) * VSTR + pos] = pack_h2(v0.w, v1.w);
        }
        __syncthreads();

        // ---- S = Q @ K^T  (warp: 32 q x 64 keys, mt=2) ----
        float s[2][8][4];
#pragma unroll
        for (int mt = 0; mt < 2; mt++)
#pragma unroll
            for (int nt = 0; nt < 8; nt++)
#pragma unroll
                for (int q = 0; q < 4; q++) s[mt][nt][q] = 0.f;

#pragma unroll
        for (int ks = 0; ks < 8; ks++) {
            const int kcol = ks * 8 + 2 * tg;
            uint2 qf[2][2];
            qf[0][0] = *(const uint2*)&Qs[(wr + g) * ASTR + kcol];
            qf[0][1] = *(const uint2*)&Qs[(wr + g + 8) * ASTR + kcol];
            qf[1][0] = *(const uint2*)&Qs[(wr + 16 + g) * ASTR + kcol];
            qf[1][1] = *(const uint2*)&Qs[(wr + 24 + g) * ASTR + kcol];
#pragma unroll
            for (int nt = 0; nt < 8; nt++) {
                uint2 bf = *(const uint2*)&Ks[(nt * 8 + g) * ASTR + kcol];
#pragma unroll
                for (int mt = 0; mt < 2; mt++)
                    mma_tf32(s[mt][nt],
                             qf[mt][0].x, qf[mt][1].x, qf[mt][0].y, qf[mt][1].y,
                             bf.x, bf.y);
            }
        }

        // ---- online softmax; pack P to half2 in registers ----
        uint32_t ph[2][8][2];
#pragma unroll
        for (int mt = 0; mt < 2; mt++) {
            float mx0 = -1e30f, mx1 = -1e30f;
#pragma unroll
            for (int nt = 0; nt < 8; nt++) {
                mx0 = fmaxf(mx0, fmaxf(s[mt][nt][0], s[mt][nt][1]));
                mx1 = fmaxf(mx1, fmaxf(s[mt][nt][2], s[mt][nt][3]));
            }
            mx0 = fmaxf(mx0, __shfl_xor_sync(0xffffffffu, mx0, 1));
            mx0 = fmaxf(mx0, __shfl_xor_sync(0xffffffffu, mx0, 2));
            mx1 = fmaxf(mx1, __shfl_xor_sync(0xffffffffu, mx1, 1));
            mx1 = fmaxf(mx1, __shfl_xor_sync(0xffffffffu, mx1, 2));
            const float mn0 = fmaxf(mrow[mt][0], mx0);
            const float mn1 = fmaxf(mrow[mt][1], mx1);
            const float al0 = __expf(mrow[mt][0] - mn0);
            const float al1 = __expf(mrow[mt][1] - mn1);
            mrow[mt][0] = mn0; mrow[mt][1] = mn1;

            float sum0 = 0.f, sum1 = 0.f;
#pragma unroll
            for (int nt = 0; nt < 8; nt++) {
                float p0 = __expf(s[mt][nt][0] - mn0);
                float p1 = __expf(s[mt][nt][1] - mn0);
                float p2 = __expf(s[mt][nt][2] - mn1);
                float p3 = __expf(s[mt][nt][3] - mn1);
                sum0 += p0 + p1; sum1 += p2 + p3;
                ph[mt][nt][0] = pack_h2(p0, p1);   // row g,   keys 8nt+2tg,+1
                ph[mt][nt][1] = pack_h2(p2, p3);   // row g+8
                o[mt][nt][0] *= al0; o[mt][nt][1] *= al0;
                o[mt][nt][2] *= al1; o[mt][nt][3] *= al1;
            }
            sum0 += __shfl_xor_sync(0xffffffffu, sum0, 1);
            sum0 += __shfl_xor_sync(0xffffffffu, sum0, 2);
            sum1 += __shfl_xor_sync(0xffffffffu, sum1, 1);
            sum1 += __shfl_xor_sync(0xffffffffu, sum1, 2);
            lrow[mt][0] = lrow[mt][0] * al0 + sum0;
            lrow[mt][1] = lrow[mt][1] * al1 + sum1;
        }

        // ---- O += P @ V  (fp16 m16n8k16, P from registers) ----
#pragma unroll
        for (int kc = 0; kc < 4; kc++) {
            const int vcol = kc * 8 + 2 * tg;
#pragma unroll
            for (int nt = 0; nt < 8; nt++) {
                uint2 bf = *(const uint2*)&Vt[(nt * 8 + g) * VSTR + vcol];
#pragma unroll
                for (int mt = 0; mt < 2; mt++)
                    mma_fp16(o[mt][nt],
                             ph[mt][2 * kc][0], ph[mt][2 * kc][1],
                             ph[mt][2 * kc + 1][0], ph[mt][2 * kc + 1][1],
                             bf.x, bf.y);
            }
        }
        __syncthreads();   // Ks/Vt consumed before restaging
    }

    // ---- normalize + store ctx in [b, s, h*64+dh] layout ----
#pragma unroll
    for (int mt = 0; mt < 2; mt++) {
        const float li0 = 1.f / lrow[mt][0];
        const float li1 = 1.f / lrow[mt][1];
        const size_t r0 = base + (size_t)(qb * 128 + wr + mt * 16 + g) * DMODEL;
        const size_t r1 = r0 + (size_t)8 * DMODEL;
#pragma unroll
        for (int nt = 0; nt < 8; nt++) {
            const int col = nt * 8 + 2 * tg;
            *(float2*)(C + r0 + col) = make_float2(o[mt][nt][0] * li0, o[mt][nt][1] * li0);
            *(float2*)(C + r1 + col) = make_float2(o[mt][nt][2] * li1, o[mt][nt][3] * li1);
        }
    }
}

// ---------------------------------------------------------------------------
// Launch
// ---------------------------------------------------------------------------
extern "C" void kernel_launch(void* const* d_in, const int* in_sizes, int n_in,
                              void* d_out, int out_size)
{
    const float* X  = (const float*)d_in[0];
    const float* Wq = (const float*)d_in[1];
    const float* bq = (const float*)d_in[2];
    const float* Wk = (const float*)d_in[3];
    const float* bk = (const float*)d_in[4];
    const float* Wv = (const float*)d_in[5];
    const float* bv = (const float*)d_in[6];
    const float* Wo = (const float*)d_in[7];
    const float* bo = (const float*)d_in[8];
    float* out = (float*)d_out;

    float *Qp, *Kp, *Vp, *Cp;
    cudaGetSymbolAddress((void**)&Qp, g_Q);
    cudaGetSymbolAddress((void**)&Kp, g_K);
    cudaGetSymbolAddress((void**)&Vp, g_V);
    cudaGetSymbolAddress((void**)&Cp, g_C);

    static bool attr_set = false;
    if (!attr_set) {
        cudaFuncSetAttribute(attention_tc,
                             cudaFuncAttributeMaxDynamicSharedMemorySize,
                             ATT_SMEM_U32 * (int)sizeof(uint32_t));
        cudaFuncSetAttribute(gemm_tf32_nt,
                             cudaFuncAttributeMaxDynamicSharedMemorySize,
                             GEMM_SMEM_U32 * (int)sizeof(uint32_t));
        attr_set = true;
    }

    const int gemm_smem = GEMM_SMEM_U32 * sizeof(uint32_t);
    dim3 gemm_grid(DMODEL / 128, MROWS / 128);   // (8, 128)
    gemm_tf32_nt<<<gemm_grid, 256, gemm_smem>>>(X, Wq, bq, Qp, MROWS, DMODEL, DMODEL);
    gemm_tf32_nt<<<gemm_grid, 256, gemm_smem>>>(X, Wk, bk, Kp, MROWS, DMODEL, DMODEL);
    gemm_tf32_nt<<<gemm_grid, 256, gemm_smem>>>(X, Wv, bv, Vp, MROWS, DMODEL, DMODEL);

    dim3 att_grid(SEQ / 128, NHEAD, BATCH);      // (8, 16, 16)
    attention_tc<<<att_grid, 128, ATT_SMEM_U32 * sizeof(uint32_t)>>>(Qp, Kp, Vp, Cp);

    gemm_tf32_nt<<<gemm_grid, 256, gemm_smem>>>(Cp, Wo, bo, out, MROWS, DMODEL, DMODEL);
}

// round 8
// speedup vs baseline: 3.3827x; 1.0580x over previous
#include <cuda_runtime.h>
#include <cuda_fp16.h>
#include <cstdint>
#include <math.h>

// ---------------------------------------------------------------------------
// AttentionActPrune: full MHA block. B=16, S=1024, d=1024, H=16, Dh=64.
// Round 8: GEMM rebuilt — BK=16 double-buffered, 128 threads, 64x64 warp tile
//          (0.5 LDS/MMA), 41KB static smem (2 CTAs/SM), 32-reg prefetch.
//          Attention unchanged from R7 (430us).
// ---------------------------------------------------------------------------

#define BATCH   16
#define SEQ     1024
#define DMODEL  1024
#define NHEAD   16
#define DHEAD   64
#define MROWS   (BATCH * SEQ)          // 16384

__device__ float g_Q[(size_t)MROWS * DMODEL];
__device__ float g_K[(size_t)MROWS * DMODEL];
__device__ float g_V[(size_t)MROWS * DMODEL];
__device__ float g_C[(size_t)MROWS * DMODEL];

__device__ __forceinline__ uint32_t f2tf32(float f) {
    uint32_t u;
    asm("cvt.rna.tf32.f32 %0, %1;" : "=r"(u) : "f"(f));
    return u;
}

__device__ __forceinline__ void mma_tf32(float* c, uint32_t a0, uint32_t a1,
                                         uint32_t a2, uint32_t a3,
                                         uint32_t b0, uint32_t b1) {
    asm volatile(
        "mma.sync.aligned.m16n8k8.row.col.f32.tf32.tf32.f32 "
        "{%0,%1,%2,%3}, {%4,%5,%6,%7}, {%8,%9}, {%0,%1,%2,%3};"
        : "+f"(c[0]), "+f"(c[1]), "+f"(c[2]), "+f"(c[3])
        : "r"(a0), "r"(a1), "r"(a2), "r"(a3), "r"(b0), "r"(b1));
}

__device__ __forceinline__ void mma_fp16(float* c, uint32_t a0, uint32_t a1,
                                         uint32_t a2, uint32_t a3,
                                         uint32_t b0, uint32_t b1) {
    asm volatile(
        "mma.sync.aligned.m16n8k16.row.col.f32.f16.f16.f32 "
        "{%0,%1,%2,%3}, {%4,%5,%6,%7}, {%8,%9}, {%0,%1,%2,%3};"
        : "+f"(c[0]), "+f"(c[1]), "+f"(c[2]), "+f"(c[3])
        : "r"(a0), "r"(a1), "r"(a2), "r"(a3), "r"(b0), "r"(b1));
}

__device__ __forceinline__ uint32_t pack_h2(float lo, float hi) {
    __half2 h = __floats2half2_rn(lo, hi);
    return *(uint32_t*)&h;
}

// ---------------------------------------------------------------------------
// tf32 GEMM (NT), BK=16 double-buffered: C[m,n] = sum_k A[m,k]*B[n,k]+bias[n]
// 128 threads, 4 warps (2x2), warp tile 64x64 (mt=4, nt=8).
// Smem: 2 stages x (A,B) x 128 rows x 20 u32 = 41KB static -> 2 CTAs/SM.
// Register prefetch (4 float4 per matrix per thread) overlaps the MMA phase.
// k-pair permutation: within each 8-group, k -> 2*(k&3) + (k>>2); fragment
// (k, k+4) is one aligned LDS.64. Fragment banks (10g+2tg): conflict-free.
// ---------------------------------------------------------------------------
#define GSTR 20
#define GBUF (128 * GSTR)

__global__ __launch_bounds__(128)
void gemm_tf32_nt(const float* __restrict__ A, const float* __restrict__ B,
                  const float* __restrict__ bias, float* __restrict__ C,
                  int M, int N, int K)
{
    __shared__ uint32_t sA[2 * GBUF];
    __shared__ uint32_t sB[2 * GBUF];

    const int tid  = threadIdx.x;
    const int wid  = tid >> 5;
    const int lane = tid & 31;
    const int g    = lane >> 2;
    const int tg   = lane & 3;
    const int warp_m = wid & 1;          // 2 warps along M (64 rows)
    const int warp_n = wid >> 1;         // 2 warps along N (64 cols)
    const int bm = blockIdx.y * 128;
    const int bn = blockIdx.x * 128;

    // staging: 128 rows x 4 float4 = 512 tasks per matrix; 4 per thread
    float4 pa[4], pb[4];
#pragma unroll
    for (int i = 0; i < 4; i++) {
        int idx = tid + i * 128;
        int r = idx >> 2, c = idx & 3;
        pa[i] = *(const float4*)(A + (size_t)(bm + r) * K + c * 4);
        pb[i] = *(const float4*)(B + (size_t)(bn + r) * K + c * 4);
    }

    float acc[4][8][4];
#pragma unroll
    for (int i = 0; i < 4; i++)
#pragma unroll
        for (int j = 0; j < 8; j++)
#pragma unroll
            for (int q = 0; q < 4; q++) acc[i][j][q] = 0.f;

    const int nkc = K / 16;
    for (int kc = 0; kc < nkc; kc++) {
        uint32_t* bufA = sA + (kc & 1) * GBUF;
        uint32_t* bufB = sB + (kc & 1) * GBUF;
#pragma unroll
        for (int i = 0; i < 4; i++) {
            int idx = tid + i * 128;
            int r = idx >> 2, c = idx & 3;
            int base = r * GSTR + (c >> 1) * 8 + (c & 1);
            bufA[base + 0] = f2tf32(pa[i].x);
            bufA[base + 2] = f2tf32(pa[i].y);
            bufA[base + 4] = f2tf32(pa[i].z);
            bufA[base + 6] = f2tf32(pa[i].w);
            bufB[base + 0] = f2tf32(pb[i].x);
            bufB[base + 2] = f2tf32(pb[i].y);
            bufB[base + 4] = f2tf32(pb[i].z);
            bufB[base + 6] = f2tf32(pb[i].w);
        }
        __syncthreads();

        // prefetch next stage (overlaps MMA below; lands in the other buffer)
        if (kc + 1 < nkc) {
            const int k0n = (kc + 1) * 16;
#pragma unroll
            for (int i = 0; i < 4; i++) {
                int idx = tid + i * 128;
                int r = idx >> 2, c = idx & 3;
                pa[i] = *(const float4*)(A + (size_t)(bm + r) * K + k0n + c * 4);
                pb[i] = *(const float4*)(B + (size_t)(bn + r) * K + k0n + c * 4);
            }
        }

#pragma unroll
        for (int ks = 0; ks < 2; ks++) {
            const int kcol = ks * 8 + 2 * tg;
            uint2 aLo[4], aHi[4];
#pragma unroll
            for (int mt = 0; mt < 4; mt++) {
                int r = warp_m * 64 + mt * 16 + g;
                aLo[mt] = *(const uint2*)&bufA[r * GSTR + kcol];
                aHi[mt] = *(const uint2*)&bufA[(r + 8) * GSTR + kcol];
            }
            uint2 bf[8];
#pragma unroll
            for (int nt = 0; nt < 8; nt++) {
                int rn = warp_n * 64 + nt * 8 + g;
                bf[nt] = *(const uint2*)&bufB[rn * GSTR + kcol];
            }
#pragma unroll
            for (int mt = 0; mt < 4; mt++)
#pragma unroll
                for (int nt = 0; nt < 8; nt++)
                    mma_tf32(acc[mt][nt],
                             aLo[mt].x, aHi[mt].x, aLo[mt].y, aHi[mt].y,
                             bf[nt].x, bf[nt].y);
        }
        // no trailing barrier: next iteration writes the OTHER buffer; the
        // barrier above (between STS and MMA) provides the ordering.
    }

#pragma unroll
    for (int mt = 0; mt < 4; mt++) {
        const int row0 = bm + warp_m * 64 + mt * 16 + g;
#pragma unroll
        for (int nt = 0; nt < 8; nt++) {
            const int col = bn + warp_n * 64 + nt * 8 + 2 * tg;
            const float b0 = bias[col], b1 = bias[col + 1];
            float2 v0 = make_float2(acc[mt][nt][0] + b0, acc[mt][nt][1] + b1);
            float2 v1 = make_float2(acc[mt][nt][2] + b0, acc[mt][nt][3] + b1);
            *(float2*)(C + (size_t)row0 * N + col) = v0;
            *(float2*)(C + (size_t)(row0 + 8) * N + col) = v1;
        }
    }
}

// ---------------------------------------------------------------------------
// Tensor-core flash attention (unchanged from R7, 430us).
// CTA = 128 q-rows, 128 threads, 4 warps x 32 rows (mt=2). KB=64 keys/iter.
// QK: tf32 m16n8k8. PV: fp16 m16n8k16, P register-resident, V half2 key-pairs.
// ---------------------------------------------------------------------------
#define ASTR 74
#define VSTR 42
#define Q_U32 (128 * ASTR)
#define K_U32 (64 * ASTR)
#define V_U32 (64 * VSTR)
#define ATT_SMEM_U32 (Q_U32 + K_U32 + V_U32)   // 16896 u32 = 67584 B

__global__ __launch_bounds__(128, 2)
void attention_tc(const float* __restrict__ Q, const float* __restrict__ K,
                  const float* __restrict__ V, float* __restrict__ C)
{
    extern __shared__ uint32_t sm[];
    uint32_t* Qs = sm;
    uint32_t* Ks = sm + Q_U32;
    uint32_t* Vt = Ks + K_U32;

    const int tid  = threadIdx.x;
    const int wid  = tid >> 5;
    const int lane = tid & 31;
    const int g    = lane >> 2;
    const int tg   = lane & 3;
    const int qb = blockIdx.x;
    const int h  = blockIdx.y;
    const int b  = blockIdx.z;
    const size_t base = (size_t)b * SEQ * DMODEL + (size_t)h * DHEAD;
    const int wr = wid * 32;

#pragma unroll
    for (int i = 0; i < 16; i++) {
        int idx = tid + i * 128;
        int r = idx >> 4, c = idx & 15;
        float4 v = *(const float4*)(Q + base + (size_t)(qb * 128 + r) * DMODEL + c * 4);
        int p0 = r * ASTR + (c >> 1) * 8 + (c & 1);
        Qs[p0 + 0] = f2tf32(v.x * 0.125f);
        Qs[p0 + 2] = f2tf32(v.y * 0.125f);
        Qs[p0 + 4] = f2tf32(v.z * 0.125f);
        Qs[p0 + 6] = f2tf32(v.w * 0.125f);
    }
    __syncthreads();

    float o[2][8][4];
#pragma unroll
    for (int mt = 0; mt < 2; mt++)
#pragma unroll
        for (int nt = 0; nt < 8; nt++)
#pragma unroll
            for (int q = 0; q < 4; q++) o[mt][nt][q] = 0.f;
    float mrow[2][2], lrow[2][2];
#pragma unroll
    for (int mt = 0; mt < 2; mt++) {
        mrow[mt][0] = mrow[mt][1] = -1e30f;
        lrow[mt][0] = lrow[mt][1] = 0.f;
    }

    for (int kb = 0; kb < SEQ / 64; kb++) {
#pragma unroll
        for (int i = 0; i < 8; i++) {
            int idx = tid + i * 128;
            int key = idx >> 4, c = idx & 15;
            float4 kv = *(const float4*)(K + base + (size_t)(kb * 64 + key) * DMODEL + c * 4);
            int p0 = key * ASTR + (c >> 1) * 8 + (c & 1);
            Ks[p0 + 0] = f2tf32(kv.x);
            Ks[p0 + 2] = f2tf32(kv.y);
            Ks[p0 + 4] = f2tf32(kv.z);
            Ks[p0 + 6] = f2tf32(kv.w);
        }
#pragma unroll
        for (int i = 0; i < 4; i++) {
            int t = tid + i * 128;
            int p  = t >> 4;
            int dc = t & 15;
            const float* vb = V + base + (size_t)(kb * 64 + 2 * p) * DMODEL + dc * 4;
            float4 v0 = *(const float4*)(vb);
            float4 v1 = *(const float4*)(vb + DMODEL);
            int pos = (p & ~7) + 2 * (p & 3) + ((p >> 2) & 1);
            Vt[(dc * 4 + 0) * VSTR + pos] = pack_h2(v0.x, v1.x);
            Vt[(dc * 4 + 1) * VSTR + pos] = pack_h2(v0.y, v1.y);
            Vt[(dc * 4 + 2) * VSTR + pos] = pack_h2(v0.z, v1.z);
            Vt[(dc * 4 + 3) * VSTR + pos] = pack_h2(v0.w, v1.w);
        }
        __syncthreads();

        float s[2][8][4];
#pragma unroll
        for (int mt = 0; mt < 2; mt++)
#pragma unroll
            for (int nt = 0; nt < 8; nt++)
#pragma unroll
                for (int q = 0; q < 4; q++) s[mt][nt][q] = 0.f;

#pragma unroll
        for (int ks = 0; ks < 8; ks++) {
            const int kcol = ks * 8 + 2 * tg;
            uint2 qf[2][2];
            qf[0][0] = *(const uint2*)&Qs[(wr + g) * ASTR + kcol];
            qf[0][1] = *(const uint2*)&Qs[(wr + g + 8) * ASTR + kcol];
            qf[1][0] = *(const uint2*)&Qs[(wr + 16 + g) * ASTR + kcol];
            qf[1][1] = *(const uint2*)&Qs[(wr + 24 + g) * ASTR + kcol];
#pragma unroll
            for (int nt = 0; nt < 8; nt++) {
                uint2 bf = *(const uint2*)&Ks[(nt * 8 + g) * ASTR + kcol];
#pragma unroll
                for (int mt = 0; mt < 2; mt++)
                    mma_tf32(s[mt][nt],
                             qf[mt][0].x, qf[mt][1].x, qf[mt][0].y, qf[mt][1].y,
                             bf.x, bf.y);
            }
        }

        uint32_t ph[2][8][2];
#pragma unroll
        for (int mt = 0; mt < 2; mt++) {
            float mx0 = -1e30f, mx1 = -1e30f;
#pragma unroll
            for (int nt = 0; nt < 8; nt++) {
                mx0 = fmaxf(mx0, fmaxf(s[mt][nt][0], s[mt][nt][1]));
                mx1 = fmaxf(mx1, fmaxf(s[mt][nt][2], s[mt][nt][3]));
            }
            mx0 = fmaxf(mx0, __shfl_xor_sync(0xffffffffu, mx0, 1));
            mx0 = fmaxf(mx0, __shfl_xor_sync(0xffffffffu, mx0, 2));
            mx1 = fmaxf(mx1, __shfl_xor_sync(0xffffffffu, mx1, 1));
            mx1 = fmaxf(mx1, __shfl_xor_sync(0xffffffffu, mx1, 2));
            const float mn0 = fmaxf(mrow[mt][0], mx0);
            const float mn1 = fmaxf(mrow[mt][1], mx1);
            const float al0 = __expf(mrow[mt][0] - mn0);
            const float al1 = __expf(mrow[mt][1] - mn1);
            mrow[mt][0] = mn0; mrow[mt][1] = mn1;

            float sum0 = 0.f, sum1 = 0.f;
#pragma unroll
            for (int nt = 0; nt < 8; nt++) {
                float p0 = __expf(s[mt][nt][0] - mn0);
                float p1 = __expf(s[mt][nt][1] - mn0);
                float p2 = __expf(s[mt][nt][2] - mn1);
                float p3 = __expf(s[mt][nt][3] - mn1);
                sum0 += p0 + p1; sum1 += p2 + p3;
                ph[mt][nt][0] = pack_h2(p0, p1);
                ph[mt][nt][1] = pack_h2(p2, p3);
                o[mt][nt][0] *= al0; o[mt][nt][1] *= al0;
                o[mt][nt][2] *= al1; o[mt][nt][3] *= al1;
            }
            sum0 += __shfl_xor_sync(0xffffffffu, sum0, 1);
            sum0 += __shfl_xor_sync(0xffffffffu, sum0, 2);
            sum1 += __shfl_xor_sync(0xffffffffu, sum1, 1);
            sum1 += __shfl_xor_sync(0xffffffffu, sum1, 2);
            lrow[mt][0] = lrow[mt][0] * al0 + sum0;
            lrow[mt][1] = lrow[mt][1] * al1 + sum1;
        }

#pragma unroll
        for (int kc = 0; kc < 4; kc++) {
            const int vcol = kc * 8 + 2 * tg;
#pragma unroll
            for (int nt = 0; nt < 8; nt++) {
                uint2 bf = *(const uint2*)&Vt[(nt * 8 + g) * VSTR + vcol];
#pragma unroll
                for (int mt = 0; mt < 2; mt++)
                    mma_fp16(o[mt][nt],
                             ph[mt][2 * kc][0], ph[mt][2 * kc][1],
                             ph[mt][2 * kc + 1][0], ph[mt][2 * kc + 1][1],
                             bf.x, bf.y);
            }
        }
        __syncthreads();
    }

#pragma unroll
    for (int mt = 0; mt < 2; mt++) {
        const float li0 = 1.f / lrow[mt][0];
        const float li1 = 1.f / lrow[mt][1];
        const size_t r0 = base + (size_t)(qb * 128 + wr + mt * 16 + g) * DMODEL;
        const size_t r1 = r0 + (size_t)8 * DMODEL;
#pragma unroll
        for (int nt = 0; nt < 8; nt++) {
            const int col = nt * 8 + 2 * tg;
            *(float2*)(C + r0 + col) = make_float2(o[mt][nt][0] * li0, o[mt][nt][1] * li0);
            *(float2*)(C + r1 + col) = make_float2(o[mt][nt][2] * li1, o[mt][nt][3] * li1);
        }
    }
}

// ---------------------------------------------------------------------------
// Launch
// ---------------------------------------------------------------------------
extern "C" void kernel_launch(void* const* d_in, const int* in_sizes, int n_in,
                              void* d_out, int out_size)
{
    const float* X  = (const float*)d_in[0];
    const float* Wq = (const float*)d_in[1];
    const float* bq = (const float*)d_in[2];
    const float* Wk = (const float*)d_in[3];
    const float* bk = (const float*)d_in[4];
    const float* Wv = (const float*)d_in[5];
    const float* bv = (const float*)d_in[6];
    const float* Wo = (const float*)d_in[7];
    const float* bo = (const float*)d_in[8];
    float* out = (float*)d_out;

    float *Qp, *Kp, *Vp, *Cp;
    cudaGetSymbolAddress((void**)&Qp, g_Q);
    cudaGetSymbolAddress((void**)&Kp, g_K);
    cudaGetSymbolAddress((void**)&Vp, g_V);
    cudaGetSymbolAddress((void**)&Cp, g_C);

    static bool attr_set = false;
    if (!attr_set) {
        cudaFuncSetAttribute(attention_tc,
                             cudaFuncAttributeMaxDynamicSharedMemorySize,
                             ATT_SMEM_U32 * (int)sizeof(uint32_t));
        attr_set = true;
    }

    dim3 gemm_grid(DMODEL / 128, MROWS / 128);   // (8, 128)
    gemm_tf32_nt<<<gemm_grid, 128>>>(X, Wq, bq, Qp, MROWS, DMODEL, DMODEL);
    gemm_tf32_nt<<<gemm_grid, 128>>>(X, Wk, bk, Kp, MROWS, DMODEL, DMODEL);
    gemm_tf32_nt<<<gemm_grid, 128>>>(X, Wv, bv, Vp, MROWS, DMODEL, DMODEL);

    dim3 att_grid(SEQ / 128, NHEAD, BATCH);      // (8, 16, 16)
    attention_tc<<<att_grid, 128, ATT_SMEM_U32 * sizeof(uint32_t)>>>(Qp, Kp, Vp, Cp);

    gemm_tf32_nt<<<gemm_grid, 128>>>(Cp, Wo, bo, out, MROWS, DMODEL, DMODEL);
}

// round 9
// speedup vs baseline: 3.7400x; 1.1056x over previous
#include <cuda_runtime.h>
#include <cuda_fp16.h>
#include <cstdint>
#include <math.h>

// ---------------------------------------------------------------------------
// AttentionActPrune: full MHA block. B=16, S=1024, d=1024, H=16, Dh=64.
// Round 9: GEMM — cp.async 3-stage pipeline (no register staging), natural
//          layout with k-relabeled fragments, inputs pre-rounded to tf32-RN
//          by a cvt pass (X, weights) / attention epilogue (ctx).
//          Attention core unchanged from R7/R8 (430us).
// ---------------------------------------------------------------------------

#define BATCH   16
#define SEQ     1024
#define DMODEL  1024
#define NHEAD   16
#define DHEAD   64
#define MROWS   (BATCH * SEQ)          // 16384

__device__ float g_Q[(size_t)MROWS * DMODEL];
__device__ float g_K[(size_t)MROWS * DMODEL];
__device__ float g_V[(size_t)MROWS * DMODEL];
__device__ float g_C[(size_t)MROWS * DMODEL];
__device__ float g_Xc[(size_t)MROWS * DMODEL];          // tf32-RN'd X
__device__ float g_Wc[4][(size_t)DMODEL * DMODEL];      // tf32-RN'd weights

__device__ __forceinline__ uint32_t f2tf32(float f) {
    uint32_t u;
    asm("cvt.rna.tf32.f32 %0, %1;" : "=r"(u) : "f"(f));
    return u;
}

__device__ __forceinline__ void mma_tf32(float* c, uint32_t a0, uint32_t a1,
                                         uint32_t a2, uint32_t a3,
                                         uint32_t b0, uint32_t b1) {
    asm volatile(
        "mma.sync.aligned.m16n8k8.row.col.f32.tf32.tf32.f32 "
        "{%0,%1,%2,%3}, {%4,%5,%6,%7}, {%8,%9}, {%0,%1,%2,%3};"
        : "+f"(c[0]), "+f"(c[1]), "+f"(c[2]), "+f"(c[3])
        : "r"(a0), "r"(a1), "r"(a2), "r"(a3), "r"(b0), "r"(b1));
}

__device__ __forceinline__ void mma_fp16(float* c, uint32_t a0, uint32_t a1,
                                         uint32_t a2, uint32_t a3,
                                         uint32_t b0, uint32_t b1) {
    asm volatile(
        "mma.sync.aligned.m16n8k16.row.col.f32.f16.f16.f32 "
        "{%0,%1,%2,%3}, {%4,%5,%6,%7}, {%8,%9}, {%0,%1,%2,%3};"
        : "+f"(c[0]), "+f"(c[1]), "+f"(c[2]), "+f"(c[3])
        : "r"(a0), "r"(a1), "r"(a2), "r"(a3), "r"(b0), "r"(b1));
}

__device__ __forceinline__ uint32_t pack_h2(float lo, float hi) {
    __half2 h = __floats2half2_rn(lo, hi);
    return *(uint32_t*)&h;
}

__device__ __forceinline__ uint32_t smem_u32ptr(const void* p) {
    uint32_t a;
    asm("{ .reg .u64 t; cvta.to.shared.u64 t, %1; cvt.u32.u64 %0, t; }"
        : "=r"(a) : "l"(p));
    return a;
}

__device__ __forceinline__ void cp_async16(uint32_t s, const void* g) {
    asm volatile("cp.async.cg.shared.global [%0], [%1], 16;" :: "r"(s), "l"(g));
}

// ---------------------------------------------------------------------------
// tf32-RN conversion pass (elementwise, float4)
// ---------------------------------------------------------------------------
__global__ __launch_bounds__(256)
void cvt_tf32(const float* __restrict__ in, float* __restrict__ out) {
    size_t i = ((size_t)blockIdx.x * 256 + threadIdx.x) * 4;
    float4 v = *(const float4*)(in + i);
    v.x = __uint_as_float(f2tf32(v.x));
    v.y = __uint_as_float(f2tf32(v.y));
    v.z = __uint_as_float(f2tf32(v.z));
    v.w = __uint_as_float(f2tf32(v.w));
    *(float4*)(out + i) = v;
}

// ---------------------------------------------------------------------------
// tf32 GEMM (NT), cp.async 3-stage: C[m,n] = sum_k A[m,k]*B[n,k] + bias[n]
// A,B must already be tf32-RN-valued fp32. 128 threads, 4 warps (2x2),
// warp tile 64x64 (mt=4, nt=8), BK=16. Natural smem layout (stride 20 u32);
// fragments use the k-relabeling (cols 2tg,2tg+1 -> slots tg,tg+4 for BOTH
// operands), so no staging permutation is needed and cp.async 16B works.
// ---------------------------------------------------------------------------
#define GSTR 20
#define GST_U32   (128 * GSTR)          // 2560 u32 per matrix per stage
#define GSTAGE_U32 (2 * GST_U32)        // 5120 u32 per stage (A then B)
#define GEMM_SMEM_BYTES (3 * GSTAGE_U32 * 4)   // 61440 B

__global__ __launch_bounds__(128)
void gemm_tf32_nt(const float* __restrict__ A, const float* __restrict__ B,
                  const float* __restrict__ bias, float* __restrict__ C,
                  int M, int N, int K)
{
    extern __shared__ uint32_t gsm[];
    const uint32_t smem_base = smem_u32ptr(gsm);

    const int tid  = threadIdx.x;
    const int wid  = tid >> 5;
    const int lane = tid & 31;
    const int g    = lane >> 2;
    const int tg   = lane & 3;
    const int warp_m = wid & 1;          // 2 warps along M (64 rows)
    const int warp_n = wid >> 1;         // 2 warps along N (64 cols)
    const int bm = blockIdx.y * 128;
    const int bn = blockIdx.x * 128;

    // staging tasks: idx = tid + i*128, i<4 -> 512 tasks; r=idx>>2, c=idx&3
    const int sr = tid >> 2;             // base row for i=0 (r advances +32/i)
    const int sc = tid & 3;              // 16B chunk within row

    auto issue_stage = [&](int stage, int k0) {
        const uint32_t sa = smem_base + (uint32_t)stage * GSTAGE_U32 * 4;
        const uint32_t sb = sa + GST_U32 * 4;
#pragma unroll
        for (int i = 0; i < 4; i++) {
            const int r = sr + i * 32;
            const uint32_t off = (uint32_t)(r * GSTR + sc * 4) * 4;
            cp_async16(sa + off, A + (size_t)(bm + r) * K + k0 + sc * 4);
            cp_async16(sb + off, B + (size_t)(bn + r) * K + k0 + sc * 4);
        }
        asm volatile("cp.async.commit_group;" ::: "memory");
    };

    issue_stage(0, 0);
    issue_stage(1, 16);
    issue_stage(2, 32);

    float acc[4][8][4];
#pragma unroll
    for (int i = 0; i < 4; i++)
#pragma unroll
        for (int j = 0; j < 8; j++)
#pragma unroll
            for (int q = 0; q < 4; q++) acc[i][j][q] = 0.f;

    const int nkc = K / 16;              // 64
    for (int kc = 0; kc < nkc; kc++) {
        asm volatile("cp.async.wait_group 2;" ::: "memory");
        __syncthreads();                 // stage kc%3 visible to all threads

        const uint32_t* bufA = gsm + (kc % 3) * GSTAGE_U32;
        const uint32_t* bufB = bufA + GST_U32;

#pragma unroll
        for (int ks = 0; ks < 2; ks++) {
            const int kcol = ks * 8 + 2 * tg;
            uint2 aLo[4], aHi[4];
#pragma unroll
            for (int mt = 0; mt < 4; mt++) {
                int r = warp_m * 64 + mt * 16 + g;
                aLo[mt] = *(const uint2*)&bufA[r * GSTR + kcol];
                aHi[mt] = *(const uint2*)&bufA[(r + 8) * GSTR + kcol];
            }
            uint2 bf[8];
#pragma unroll
            for (int nt = 0; nt < 8; nt++) {
                int rn = warp_n * 64 + nt * 8 + g;
                bf[nt] = *(const uint2*)&bufB[rn * GSTR + kcol];
            }
#pragma unroll
            for (int mt = 0; mt < 4; mt++)
#pragma unroll
                for (int nt = 0; nt < 8; nt++)
                    mma_tf32(acc[mt][nt],
                             aLo[mt].x, aHi[mt].x, aLo[mt].y, aHi[mt].y,
                             bf[nt].x, bf[nt].y);
        }
        __syncthreads();                 // all reads of stage kc%3 done
        if (kc + 3 < nkc)
            issue_stage(kc % 3, (kc + 3) * 16);   // overwrite freed buffer
    }

#pragma unroll
    for (int mt = 0; mt < 4; mt++) {
        const int row0 = bm + warp_m * 64 + mt * 16 + g;
#pragma unroll
        for (int nt = 0; nt < 8; nt++) {
            const int col = bn + warp_n * 64 + nt * 8 + 2 * tg;
            const float b0 = bias[col], b1 = bias[col + 1];
            float2 v0 = make_float2(acc[mt][nt][0] + b0, acc[mt][nt][1] + b1);
            float2 v1 = make_float2(acc[mt][nt][2] + b0, acc[mt][nt][3] + b1);
            *(float2*)(C + (size_t)row0 * N + col) = v0;
            *(float2*)(C + (size_t)(row0 + 8) * N + col) = v1;
        }
    }
}

// ---------------------------------------------------------------------------
// Tensor-core flash attention (R7 core; epilogue now stores tf32-RN'd ctx
// so the O-projection GEMM can consume it raw).
// ---------------------------------------------------------------------------
#define ASTR 74
#define VSTR 42
#define Q_U32 (128 * ASTR)
#define K_U32 (64 * ASTR)
#define V_U32 (64 * VSTR)
#define ATT_SMEM_U32 (Q_U32 + K_U32 + V_U32)   // 16896 u32 = 67584 B

__global__ __launch_bounds__(128, 2)
void attention_tc(const float* __restrict__ Q, const float* __restrict__ K,
                  const float* __restrict__ V, float* __restrict__ C)
{
    extern __shared__ uint32_t sm[];
    uint32_t* Qs = sm;
    uint32_t* Ks = sm + Q_U32;
    uint32_t* Vt = Ks + K_U32;

    const int tid  = threadIdx.x;
    const int wid  = tid >> 5;
    const int lane = tid & 31;
    const int g    = lane >> 2;
    const int tg   = lane & 3;
    const int qb = blockIdx.x;
    const int h  = blockIdx.y;
    const int b  = blockIdx.z;
    const size_t base = (size_t)b * SEQ * DMODEL + (size_t)h * DHEAD;
    const int wr = wid * 32;

#pragma unroll
    for (int i = 0; i < 16; i++) {
        int idx = tid + i * 128;
        int r = idx >> 4, c = idx & 15;
        float4 v = *(const float4*)(Q + base + (size_t)(qb * 128 + r) * DMODEL + c * 4);
        int p0 = r * ASTR + (c >> 1) * 8 + (c & 1);
        Qs[p0 + 0] = f2tf32(v.x * 0.125f);
        Qs[p0 + 2] = f2tf32(v.y * 0.125f);
        Qs[p0 + 4] = f2tf32(v.z * 0.125f);
        Qs[p0 + 6] = f2tf32(v.w * 0.125f);
    }
    __syncthreads();

    float o[2][8][4];
#pragma unroll
    for (int mt = 0; mt < 2; mt++)
#pragma unroll
        for (int nt = 0; nt < 8; nt++)
#pragma unroll
            for (int q = 0; q < 4; q++) o[mt][nt][q] = 0.f;
    float mrow[2][2], lrow[2][2];
#pragma unroll
    for (int mt = 0; mt < 2; mt++) {
        mrow[mt][0] = mrow[mt][1] = -1e30f;
        lrow[mt][0] = lrow[mt][1] = 0.f;
    }

    for (int kb = 0; kb < SEQ / 64; kb++) {
#pragma unroll
        for (int i = 0; i < 8; i++) {
            int idx = tid + i * 128;
            int key = idx >> 4, c = idx & 15;
            float4 kv = *(const float4*)(K + base + (size_t)(kb * 64 + key) * DMODEL + c * 4);
            int p0 = key * ASTR + (c >> 1) * 8 + (c & 1);
            Ks[p0 + 0] = f2tf32(kv.x);
            Ks[p0 + 2] = f2tf32(kv.y);
            Ks[p0 + 4] = f2tf32(kv.z);
            Ks[p0 + 6] = f2tf32(kv.w);
        }
#pragma unroll
        for (int i = 0; i < 4; i++) {
            int t = tid + i * 128;
            int p  = t >> 4;
            int dc = t & 15;
            const float* vb = V + base + (size_t)(kb * 64 + 2 * p) * DMODEL + dc * 4;
            float4 v0 = *(const float4*)(vb);
            float4 v1 = *(const float4*)(vb + DMODEL);
            int pos = (p & ~7) + 2 * (p & 3) + ((p >> 2) & 1);
            Vt[(dc * 4 + 0) * VSTR + pos] = pack_h2(v0.x, v1.x);
            Vt[(dc * 4 + 1) * VSTR + pos] = pack_h2(v0.y, v1.y);
            Vt[(dc * 4 + 2) * VSTR + pos] = pack_h2(v0.z, v1.z);
            Vt[(dc * 4 + 3) * VSTR + pos] = pack_h2(v0.w, v1.w);
        }
        __syncthreads();

        float s[2][8][4];
#pragma unroll
        for (int mt = 0; mt < 2; mt++)
#pragma unroll
            for (int nt = 0; nt < 8; nt++)
#pragma unroll
                for (int q = 0; q < 4; q++) s[mt][nt][q] = 0.f;

#pragma unroll
        for (int ks = 0; ks < 8; ks++) {
            const int kcol = ks * 8 + 2 * tg;
            uint2 qf[2][2];
            qf[0][0] = *(const uint2*)&Qs[(wr + g) * ASTR + kcol];
            qf[0][1] = *(const uint2*)&Qs[(wr + g + 8) * ASTR + kcol];
            qf[1][0] = *(const uint2*)&Qs[(wr + 16 + g) * ASTR + kcol];
            qf[1][1] = *(const uint2*)&Qs[(wr + 24 + g) * ASTR + kcol];
#pragma unroll
            for (int nt = 0; nt < 8; nt++) {
                uint2 bf = *(const uint2*)&Ks[(nt * 8 + g) * ASTR + kcol];
#pragma unroll
                for (int mt = 0; mt < 2; mt++)
                    mma_tf32(s[mt][nt],
                             qf[mt][0].x, qf[mt][1].x, qf[mt][0].y, qf[mt][1].y,
                             bf.x, bf.y);
            }
        }

        uint32_t ph[2][8][2];
#pragma unroll
        for (int mt = 0; mt < 2; mt++) {
            float mx0 = -1e30f, mx1 = -1e30f;
#pragma unroll
            for (int nt = 0; nt < 8; nt++) {
                mx0 = fmaxf(mx0, fmaxf(s[mt][nt][0], s[mt][nt][1]));
                mx1 = fmaxf(mx1, fmaxf(s[mt][nt][2], s[mt][nt][3]));
            }
            mx0 = fmaxf(mx0, __shfl_xor_sync(0xffffffffu, mx0, 1));
            mx0 = fmaxf(mx0, __shfl_xor_sync(0xffffffffu, mx0, 2));
            mx1 = fmaxf(mx1, __shfl_xor_sync(0xffffffffu, mx1, 1));
            mx1 = fmaxf(mx1, __shfl_xor_sync(0xffffffffu, mx1, 2));
            const float mn0 = fmaxf(mrow[mt][0], mx0);
            const float mn1 = fmaxf(mrow[mt][1], mx1);
            const float al0 = __expf(mrow[mt][0] - mn0);
            const float al1 = __expf(mrow[mt][1] - mn1);
            mrow[mt][0] = mn0; mrow[mt][1] = mn1;

            float sum0 = 0.f, sum1 = 0.f;
#pragma unroll
            for (int nt = 0; nt < 8; nt++) {
                float p0 = __expf(s[mt][nt][0] - mn0);
                float p1 = __expf(s[mt][nt][1] - mn0);
                float p2 = __expf(s[mt][nt][2] - mn1);
                float p3 = __expf(s[mt][nt][3] - mn1);
                sum0 += p0 + p1; sum1 += p2 + p3;
                ph[mt][nt][0] = pack_h2(p0, p1);
                ph[mt][nt][1] = pack_h2(p2, p3);
                o[mt][nt][0] *= al0; o[mt][nt][1] *= al0;
                o[mt][nt][2] *= al1; o[mt][nt][3] *= al1;
            }
            sum0 += __shfl_xor_sync(0xffffffffu, sum0, 1);
            sum0 += __shfl_xor_sync(0xffffffffu, sum0, 2);
            sum1 += __shfl_xor_sync(0xffffffffu, sum1, 1);
            sum1 += __shfl_xor_sync(0xffffffffu, sum1, 2);
            lrow[mt][0] = lrow[mt][0] * al0 + sum0;
            lrow[mt][1] = lrow[mt][1] * al1 + sum1;
        }

#pragma unroll
        for (int kc = 0; kc < 4; kc++) {
            const int vcol = kc * 8 + 2 * tg;
#pragma unroll
            for (int nt = 0; nt < 8; nt++) {
                uint2 bf = *(const uint2*)&Vt[(nt * 8 + g) * VSTR + vcol];
#pragma unroll
                for (int mt = 0; mt < 2; mt++)
                    mma_fp16(o[mt][nt],
                             ph[mt][2 * kc][0], ph[mt][2 * kc][1],
                             ph[mt][2 * kc + 1][0], ph[mt][2 * kc + 1][1],
                             bf.x, bf.y);
            }
        }
        __syncthreads();
    }

    // store ctx pre-rounded to tf32-RN (the O-GEMM consumes it raw)
#pragma unroll
    for (int mt = 0; mt < 2; mt++) {
        const float li0 = 1.f / lrow[mt][0];
        const float li1 = 1.f / lrow[mt][1];
        const size_t r0 = base + (size_t)(qb * 128 + wr + mt * 16 + g) * DMODEL;
        const size_t r1 = r0 + (size_t)8 * DMODEL;
#pragma unroll
        for (int nt = 0; nt < 8; nt++) {
            const int col = nt * 8 + 2 * tg;
            float2 v0 = make_float2(
                __uint_as_float(f2tf32(o[mt][nt][0] * li0)),
                __uint_as_float(f2tf32(o[mt][nt][1] * li0)));
            float2 v1 = make_float2(
                __uint_as_float(f2tf32(o[mt][nt][2] * li1)),
                __uint_as_float(f2tf32(o[mt][nt][3] * li1)));
            *(float2*)(C + r0 + col) = v0;
            *(float2*)(C + r1 + col) = v1;
        }
    }
}

// ---------------------------------------------------------------------------
// Launch
// ---------------------------------------------------------------------------
extern "C" void kernel_launch(void* const* d_in, const int* in_sizes, int n_in,
                              void* d_out, int out_size)
{
    const float* X  = (const float*)d_in[0];
    const float* Wq = (const float*)d_in[1];
    const float* bq = (const float*)d_in[2];
    const float* Wk = (const float*)d_in[3];
    const float* bk = (const float*)d_in[4];
    const float* Wv = (const float*)d_in[5];
    const float* bv = (const float*)d_in[6];
    const float* Wo = (const float*)d_in[7];
    const float* bo = (const float*)d_in[8];
    float* out = (float*)d_out;

    float *Qp, *Kp, *Vp, *Cp, *Xc, *Wc;
    cudaGetSymbolAddress((void**)&Qp, g_Q);
    cudaGetSymbolAddress((void**)&Kp, g_K);
    cudaGetSymbolAddress((void**)&Vp, g_V);
    cudaGetSymbolAddress((void**)&Cp, g_C);
    cudaGetSymbolAddress((void**)&Xc, g_Xc);
    cudaGetSymbolAddress((void**)&Wc, g_Wc);
    float* Wc0 = Wc;
    float* Wc1 = Wc + (size_t)DMODEL * DMODEL;
    float* Wc2 = Wc + 2 * (size_t)DMODEL * DMODEL;
    float* Wc3 = Wc + 3 * (size_t)DMODEL * DMODEL;

    static bool attr_set = false;
    if (!attr_set) {
        cudaFuncSetAttribute(attention_tc,
                             cudaFuncAttributeMaxDynamicSharedMemorySize,
                             ATT_SMEM_U32 * (int)sizeof(uint32_t));
        cudaFuncSetAttribute(gemm_tf32_nt,
                             cudaFuncAttributeMaxDynamicSharedMemorySize,
                             GEMM_SMEM_BYTES);
        attr_set = true;
    }

    // pre-round inputs to tf32-RN
    const int XBLK = (MROWS * DMODEL) / (256 * 4);       // 16384
    const int WBLK = (DMODEL * DMODEL) / (256 * 4);      // 1024
    cvt_tf32<<<XBLK, 256>>>(X,  Xc);
    cvt_tf32<<<WBLK, 256>>>(Wq, Wc0);
    cvt_tf32<<<WBLK, 256>>>(Wk, Wc1);
    cvt_tf32<<<WBLK, 256>>>(Wv, Wc2);
    cvt_tf32<<<WBLK, 256>>>(Wo, Wc3);

    dim3 gemm_grid(DMODEL / 128, MROWS / 128);   // (8, 128)
    gemm_tf32_nt<<<gemm_grid, 128, GEMM_SMEM_BYTES>>>(Xc, Wc0, bq, Qp, MROWS, DMODEL, DMODEL);
    gemm_tf32_nt<<<gemm_grid, 128, GEMM_SMEM_BYTES>>>(Xc, Wc1, bk, Kp, MROWS, DMODEL, DMODEL);
    gemm_tf32_nt<<<gemm_grid, 128, GEMM_SMEM_BYTES>>>(Xc, Wc2, bv, Vp, MROWS, DMODEL, DMODEL);

    dim3 att_grid(SEQ / 128, NHEAD, BATCH);      // (8, 16, 16)
    attention_tc<<<att_grid, 128, ATT_SMEM_U32 * sizeof(uint32_t)>>>(Qp, Kp, Vp, Cp);

    gemm_tf32_nt<<<gemm_grid, 128, GEMM_SMEM_BYTES>>>(Cp, Wc3, bo, out, MROWS, DMODEL, DMODEL);
}

// round 10
// speedup vs baseline: 5.6957x; 1.5229x over previous
#include <cuda_runtime.h>
#include <cuda_fp16.h>
#include <cstdint>
#include <math.h>

// ---------------------------------------------------------------------------
// AttentionActPrune: full MHA block. B=16, S=1024, d=1024, H=16, Dh=64.
// Round 10: fp16 m16n8k16 everywhere (same 10-bit mantissa as tf32 -> same
//           rounding error). Half-precision scratch (Q/K/V/ctx), cp.async
//           3-stage GEMM, consistent k-relabel instead of permuted staging.
// ---------------------------------------------------------------------------

#define BATCH   16
#define SEQ     1024
#define DMODEL  1024
#define NHEAD   16
#define DHEAD   64
#define MROWS   (BATCH * SEQ)          // 16384

__device__ __half g_Qh[(size_t)MROWS * DMODEL];
__device__ __half g_Kh[(size_t)MROWS * DMODEL];
__device__ __half g_Vh[(size_t)MROWS * DMODEL];
__device__ __half g_Ch[(size_t)MROWS * DMODEL];
__device__ __half g_Xh[(size_t)MROWS * DMODEL];
__device__ __half g_Wh[4][(size_t)DMODEL * DMODEL];

__device__ __forceinline__ void mma_fp16(float* c, uint32_t a0, uint32_t a1,
                                         uint32_t a2, uint32_t a3,
                                         uint32_t b0, uint32_t b1) {
    asm volatile(
        "mma.sync.aligned.m16n8k16.row.col.f32.f16.f16.f32 "
        "{%0,%1,%2,%3}, {%4,%5,%6,%7}, {%8,%9}, {%0,%1,%2,%3};"
        : "+f"(c[0]), "+f"(c[1]), "+f"(c[2]), "+f"(c[3])
        : "r"(a0), "r"(a1), "r"(a2), "r"(a3), "r"(b0), "r"(b1));
}

__device__ __forceinline__ uint32_t pack_h2(float lo, float hi) {
    __half2 h = __floats2half2_rn(lo, hi);
    return *(uint32_t*)&h;
}

__device__ __forceinline__ uint32_t smem_u32ptr(const void* p) {
    uint32_t a;
    asm("{ .reg .u64 t; cvta.to.shared.u64 t, %1; cvt.u32.u64 %0, t; }"
        : "=r"(a) : "l"(p));
    return a;
}

__device__ __forceinline__ void cp_async16(uint32_t s, const void* g) {
    asm volatile("cp.async.cg.shared.global [%0], [%1], 16;" :: "r"(s), "l"(g));
}

// ---------------------------------------------------------------------------
// fp32 -> fp16 conversion pass (elementwise, float4 -> uint2)
// ---------------------------------------------------------------------------
__global__ __launch_bounds__(256)
void cvt_f32_f16(const float* __restrict__ in, __half* __restrict__ out) {
    size_t i = ((size_t)blockIdx.x * 256 + threadIdx.x) * 4;
    float4 v = *(const float4*)(in + i);
    uint2 o = make_uint2(pack_h2(v.x, v.y), pack_h2(v.z, v.w));
    *(uint2*)(out + i) = o;
}

// ---------------------------------------------------------------------------
// fp16 GEMM (NT), cp.async 3-stage: C[m,n] = sum_k A[m,k]*B[n,k] + bias[n]
// 128 threads, 4 warps (2x2), warp tile 64x64 (mt=4, nt=8), BK=32.
// Natural smem layout, stride GSTR=20 u32 (= 40 halves). Consistent
// k-relabel: uint2 at u32-col ks*8+2tg supplies MMA slots (a0,a2)/(b0,b1);
// identical mapping for A and B keeps the k-sum exact.
// OUT32=1: fp32 output (final projection), else half output.
// ---------------------------------------------------------------------------
#define GSTR 20
#define GST_U32   (128 * GSTR)
#define GSTAGE_U32 (2 * GST_U32)
#define GEMM_SMEM_BYTES (3 * GSTAGE_U32 * 4)   // 61440 B

template<int OUT32>
__global__ __launch_bounds__(128)
void gemm_f16_nt(const __half* __restrict__ A, const __half* __restrict__ B,
                 const float* __restrict__ bias, void* __restrict__ Cout,
                 int M, int N, int K)
{
    extern __shared__ uint32_t gsm[];
    const uint32_t smem_base = smem_u32ptr(gsm);

    const int tid  = threadIdx.x;
    const int wid  = tid >> 5;
    const int lane = tid & 31;
    const int g    = lane >> 2;
    const int tg   = lane & 3;
    const int warp_m = wid & 1;
    const int warp_n = wid >> 1;
    const int bm = blockIdx.y * 128;
    const int bn = blockIdx.x * 128;

    const int sr = tid >> 2;             // staging row base (advances +32/i)
    const int sc = tid & 3;              // 16B chunk (8 halves)

    auto issue_stage = [&](int stage, int k0) {
        const uint32_t sa = smem_base + (uint32_t)stage * GSTAGE_U32 * 4;
        const uint32_t sb = sa + GST_U32 * 4;
#pragma unroll
        for (int i = 0; i < 4; i++) {
            const int r = sr + i * 32;
            const uint32_t off = (uint32_t)(r * GSTR + sc * 4) * 4;
            cp_async16(sa + off, A + (size_t)(bm + r) * K + k0 + sc * 8);
            cp_async16(sb + off, B + (size_t)(bn + r) * K + k0 + sc * 8);
        }
        asm volatile("cp.async.commit_group;" ::: "memory");
    };

    issue_stage(0, 0);
    issue_stage(1, 32);
    issue_stage(2, 64);

    float acc[4][8][4];
#pragma unroll
    for (int i = 0; i < 4; i++)
#pragma unroll
        for (int j = 0; j < 8; j++)
#pragma unroll
            for (int q = 0; q < 4; q++) acc[i][j][q] = 0.f;

    const int nkc = K / 32;              // 32
    for (int kc = 0; kc < nkc; kc++) {
        asm volatile("cp.async.wait_group 2;" ::: "memory");
        __syncthreads();

        const uint32_t* bufA = gsm + (kc % 3) * GSTAGE_U32;
        const uint32_t* bufB = bufA + GST_U32;

#pragma unroll
        for (int ks = 0; ks < 2; ks++) {
            const int kcol = ks * 8 + 2 * tg;
            uint2 aLo[4], aHi[4];
#pragma unroll
            for (int mt = 0; mt < 4; mt++) {
                int r = warp_m * 64 + mt * 16 + g;
                aLo[mt] = *(const uint2*)&bufA[r * GSTR + kcol];
                aHi[mt] = *(const uint2*)&bufA[(r + 8) * GSTR + kcol];
            }
            uint2 bf[8];
#pragma unroll
            for (int nt = 0; nt < 8; nt++) {
                int rn = warp_n * 64 + nt * 8 + g;
                bf[nt] = *(const uint2*)&bufB[rn * GSTR + kcol];
            }
#pragma unroll
            for (int mt = 0; mt < 4; mt++)
#pragma unroll
                for (int nt = 0; nt < 8; nt++)
                    mma_fp16(acc[mt][nt],
                             aLo[mt].x, aHi[mt].x, aLo[mt].y, aHi[mt].y,
                             bf[nt].x, bf[nt].y);
        }
        __syncthreads();
        if (kc + 3 < nkc)
            issue_stage(kc % 3, (kc + 3) * 32);
    }

#pragma unroll
    for (int mt = 0; mt < 4; mt++) {
        const int row0 = bm + warp_m * 64 + mt * 16 + g;
#pragma unroll
        for (int nt = 0; nt < 8; nt++) {
            const int col = bn + warp_n * 64 + nt * 8 + 2 * tg;
            const float b0 = bias[col], b1 = bias[col + 1];
            if (OUT32) {
                float* C = (float*)Cout;
                *(float2*)(C + (size_t)row0 * N + col) =
                    make_float2(acc[mt][nt][0] + b0, acc[mt][nt][1] + b1);
                *(float2*)(C + (size_t)(row0 + 8) * N + col) =
                    make_float2(acc[mt][nt][2] + b0, acc[mt][nt][3] + b1);
            } else {
                __half* C = (__half*)Cout;
                *(uint32_t*)(C + (size_t)row0 * N + col) =
                    pack_h2(acc[mt][nt][0] + b0, acc[mt][nt][1] + b1);
                *(uint32_t*)(C + (size_t)(row0 + 8) * N + col) =
                    pack_h2(acc[mt][nt][2] + b0, acc[mt][nt][3] + b1);
            }
        }
    }
}

// ---------------------------------------------------------------------------
// fp16 tensor-core flash attention.
// CTA = 128 q-rows, 128 threads, 4 warps x 32 rows (mt=2). KB=64 keys/iter.
// QK: fp16 m16n8k16 (Dh=64 -> 4 k-steps), Q/K natural half layout in smem
// (stride 42 u32), consistent k-relabel as in the GEMM.
// PV: fp16 m16n8k16, P register-resident, V half2 key-pairs (R7 layout).
// ---------------------------------------------------------------------------
#define ASTR 42
#define Q_U32 (128 * ASTR)
#define K_U32 (64 * ASTR)
#define V_U32 (64 * ASTR)
#define ATT_SMEM_U32 (Q_U32 + K_U32 + V_U32)   // 10752 u32 = 43008 B

__global__ __launch_bounds__(128, 2)
void attention_tc(const __half* __restrict__ Q, const __half* __restrict__ K,
                  const __half* __restrict__ V, __half* __restrict__ C)
{
    extern __shared__ uint32_t sm[];
    uint32_t* Qs = sm;                   // half2 units, natural k order
    uint32_t* Ks = sm + Q_U32;
    uint32_t* Vt = Ks + K_U32;           // d-major, key-pair permuted

    const int tid  = threadIdx.x;
    const int wid  = tid >> 5;
    const int lane = tid & 31;
    const int g    = lane >> 2;
    const int tg   = lane & 3;
    const int qb = blockIdx.x;
    const int h  = blockIdx.y;
    const int b  = blockIdx.z;
    const size_t base = (size_t)b * SEQ * DMODEL + (size_t)h * DHEAD;
    const int wr = wid * 32;

    const __half2 hscale = __floats2half2_rn(0.125f, 0.125f);

    // ---- stage Q (scaled 1/8), half2-granular, natural layout ----
    {
        const uint32_t* qg = (const uint32_t*)(Q + base) + (size_t)(qb * 128) * (DMODEL / 2);
#pragma unroll
        for (int i = 0; i < 16; i++) {
            int t = tid + i * 128;       // 0..2047
            int r = t >> 4, c = t & 15;  // c: uint2 index (2 u32)
            uint2 v = *(const uint2*)&qg[(size_t)r * (DMODEL / 2) + c * 2];
            __half2 a = __hmul2(*(__half2*)&v.x, hscale);
            __half2 bb = __hmul2(*(__half2*)&v.y, hscale);
            Qs[r * ASTR + c * 2 + 0] = *(uint32_t*)&a;
            Qs[r * ASTR + c * 2 + 1] = *(uint32_t*)&bb;
        }
    }
    __syncthreads();

    // ---- hoist Q fragments: 4 k-steps x mt=2 x (lo,hi) uint2 ----
    uint2 qLo[2][4], qHi[2][4];
#pragma unroll
    for (int ks = 0; ks < 4; ks++) {
        const int kcol = ks * 8 + 2 * tg;
#pragma unroll
        for (int mt = 0; mt < 2; mt++) {
            qLo[mt][ks] = *(const uint2*)&Qs[(wr + mt * 16 + g) * ASTR + kcol];
            qHi[mt][ks] = *(const uint2*)&Qs[(wr + mt * 16 + g + 8) * ASTR + kcol];
        }
    }

    float o[2][8][4];
#pragma unroll
    for (int mt = 0; mt < 2; mt++)
#pragma unroll
        for (int nt = 0; nt < 8; nt++)
#pragma unroll
            for (int q = 0; q < 4; q++) o[mt][nt][q] = 0.f;
    float mrow[2][2], lrow[2][2];
#pragma unroll
    for (int mt = 0; mt < 2; mt++) {
        mrow[mt][0] = mrow[mt][1] = -1e30f;
        lrow[mt][0] = lrow[mt][1] = 0.f;
    }

    for (int kb = 0; kb < SEQ / 64; kb++) {
        // ---- stage K: straight half2 copy, natural layout ----
        {
            const uint32_t* kg = (const uint32_t*)(K + base) + (size_t)(kb * 64) * (DMODEL / 2);
#pragma unroll
            for (int i = 0; i < 8; i++) {
                int t = tid + i * 128;   // 0..1023
                int key = t >> 4, c = t & 15;
                uint2 v = *(const uint2*)&kg[(size_t)key * (DMODEL / 2) + c * 2];
                Ks[key * ASTR + c * 2 + 0] = v.x;
                Ks[key * ASTR + c * 2 + 1] = v.y;
            }
        }
        // ---- stage V: transpose to d-major half2 key-pairs ----
#pragma unroll
        for (int i = 0; i < 4; i++) {
            int t = tid + i * 128;       // 0..511
            int p  = t >> 4;             // key pair (keys 2p, 2p+1)
            int dc = t & 15;             // 4-d chunk
            const __half* vb = V + base + (size_t)(kb * 64 + 2 * p) * DMODEL + dc * 4;
            uint2 ea = *(const uint2*)(vb);                // keys 2p:   d0..d3
            uint2 eb = *(const uint2*)(vb + DMODEL);       // keys 2p+1: d0..d3
            __half2 ax = *(__half2*)&ea.x, ay = *(__half2*)&ea.y;
            __half2 bx = *(__half2*)&eb.x, by = *(__half2*)&eb.y;
            int pos = (p & ~7) + 2 * (p & 3) + ((p >> 2) & 1);
            __half2 o0 = __lows2half2(ax, bx), o1 = __highs2half2(ax, bx);
            __half2 o2 = __lows2half2(ay, by), o3 = __highs2half2(ay, by);
            Vt[(dc * 4 + 0) * ASTR + pos] = *(uint32_t*)&o0;
            Vt[(dc * 4 + 1) * ASTR + pos] = *(uint32_t*)&o1;
            Vt[(dc * 4 + 2) * ASTR + pos] = *(uint32_t*)&o2;
            Vt[(dc * 4 + 3) * ASTR + pos] = *(uint32_t*)&o3;
        }
        __syncthreads();

        // ---- S = Q @ K^T  (fp16, 4 k16-steps) ----
        float s[2][8][4];
#pragma unroll
        for (int mt = 0; mt < 2; mt++)
#pragma unroll
            for (int nt = 0; nt < 8; nt++)
#pragma unroll
                for (int q = 0; q < 4; q++) s[mt][nt][q] = 0.f;

#pragma unroll
        for (int ks = 0; ks < 4; ks++) {
            const int kcol = ks * 8 + 2 * tg;
#pragma unroll
            for (int nt = 0; nt < 8; nt++) {
                uint2 bf = *(const uint2*)&Ks[(nt * 8 + g) * ASTR + kcol];
#pragma unroll
                for (int mt = 0; mt < 2; mt++)
                    mma_fp16(s[mt][nt],
                             qLo[mt][ks].x, qHi[mt][ks].x,
                             qLo[mt][ks].y, qHi[mt][ks].y,
                             bf.x, bf.y);
            }
        }

        // ---- online softmax; pack P to half2 in registers ----
        uint32_t ph[2][8][2];
#pragma unroll
        for (int mt = 0; mt < 2; mt++) {
            float mx0 = -1e30f, mx1 = -1e30f;
#pragma unroll
            for (int nt = 0; nt < 8; nt++) {
                mx0 = fmaxf(mx0, fmaxf(s[mt][nt][0], s[mt][nt][1]));
                mx1 = fmaxf(mx1, fmaxf(s[mt][nt][2], s[mt][nt][3]));
            }
            mx0 = fmaxf(mx0, __shfl_xor_sync(0xffffffffu, mx0, 1));
            mx0 = fmaxf(mx0, __shfl_xor_sync(0xffffffffu, mx0, 2));
            mx1 = fmaxf(mx1, __shfl_xor_sync(0xffffffffu, mx1, 1));
            mx1 = fmaxf(mx1, __shfl_xor_sync(0xffffffffu, mx1, 2));
            const float mn0 = fmaxf(mrow[mt][0], mx0);
            const float mn1 = fmaxf(mrow[mt][1], mx1);
            const float al0 = __expf(mrow[mt][0] - mn0);
            const float al1 = __expf(mrow[mt][1] - mn1);
            mrow[mt][0] = mn0; mrow[mt][1] = mn1;

            float sum0 = 0.f, sum1 = 0.f;
#pragma unroll
            for (int nt = 0; nt < 8; nt++) {
                float p0 = __expf(s[mt][nt][0] - mn0);
                float p1 = __expf(s[mt][nt][1] - mn0);
                float p2 = __expf(s[mt][nt][2] - mn1);
                float p3 = __expf(s[mt][nt][3] - mn1);
                sum0 += p0 + p1; sum1 += p2 + p3;
                ph[mt][nt][0] = pack_h2(p0, p1);
                ph[mt][nt][1] = pack_h2(p2, p3);
                o[mt][nt][0] *= al0; o[mt][nt][1] *= al0;
                o[mt][nt][2] *= al1; o[mt][nt][3] *= al1;
            }
            sum0 += __shfl_xor_sync(0xffffffffu, sum0, 1);
            sum0 += __shfl_xor_sync(0xffffffffu, sum0, 2);
            sum1 += __shfl_xor_sync(0xffffffffu, sum1, 1);
            sum1 += __shfl_xor_sync(0xffffffffu, sum1, 2);
            lrow[mt][0] = lrow[mt][0] * al0 + sum0;
            lrow[mt][1] = lrow[mt][1] * al1 + sum1;
        }

        // ---- O += P @ V  (fp16, P from registers) ----
#pragma unroll
        for (int kc = 0; kc < 4; kc++) {
            const int vcol = kc * 8 + 2 * tg;
#pragma unroll
            for (int nt = 0; nt < 8; nt++) {
                uint2 bf = *(const uint2*)&Vt[(nt * 8 + g) * ASTR + vcol];
#pragma unroll
                for (int mt = 0; mt < 2; mt++)
                    mma_fp16(o[mt][nt],
                             ph[mt][2 * kc][0], ph[mt][2 * kc][1],
                             ph[mt][2 * kc + 1][0], ph[mt][2 * kc + 1][1],
                             bf.x, bf.y);
            }
        }
        __syncthreads();
    }

    // ---- normalize + store ctx (half) in [b, s, h*64+dh] layout ----
#pragma unroll
    for (int mt = 0; mt < 2; mt++) {
        const float li0 = 1.f / lrow[mt][0];
        const float li1 = 1.f / lrow[mt][1];
        const size_t r0 = base + (size_t)(qb * 128 + wr + mt * 16 + g) * DMODEL;
        const size_t r1 = r0 + (size_t)8 * DMODEL;
#pragma unroll
        for (int nt = 0; nt < 8; nt++) {
            const int col = nt * 8 + 2 * tg;
            *(uint32_t*)(C + r0 + col) = pack_h2(o[mt][nt][0] * li0, o[mt][nt][1] * li0);
            *(uint32_t*)(C + r1 + col) = pack_h2(o[mt][nt][2] * li1, o[mt][nt][3] * li1);
        }
    }
}

// ---------------------------------------------------------------------------
// Launch
// ---------------------------------------------------------------------------
extern "C" void kernel_launch(void* const* d_in, const int* in_sizes, int n_in,
                              void* d_out, int out_size)
{
    const float* X  = (const float*)d_in[0];
    const float* Wq = (const float*)d_in[1];
    const float* bq = (const float*)d_in[2];
    const float* Wk = (const float*)d_in[3];
    const float* bk = (const float*)d_in[4];
    const float* Wv = (const float*)d_in[5];
    const float* bv = (const float*)d_in[6];
    const float* Wo = (const float*)d_in[7];
    const float* bo = (const float*)d_in[8];
    float* out = (float*)d_out;

    __half *Qp, *Kp, *Vp, *Cp, *Xh, *Wh;
    cudaGetSymbolAddress((void**)&Qp, g_Qh);
    cudaGetSymbolAddress((void**)&Kp, g_Kh);
    cudaGetSymbolAddress((void**)&Vp, g_Vh);
    cudaGetSymbolAddress((void**)&Cp, g_Ch);
    cudaGetSymbolAddress((void**)&Xh, g_Xh);
    cudaGetSymbolAddress((void**)&Wh, g_Wh);
    __half* Wh0 = Wh;
    __half* Wh1 = Wh + (size_t)DMODEL * DMODEL;
    __half* Wh2 = Wh + 2 * (size_t)DMODEL * DMODEL;
    __half* Wh3 = Wh + 3 * (size_t)DMODEL * DMODEL;

    static bool attr_set = false;
    if (!attr_set) {
        cudaFuncSetAttribute(attention_tc,
                             cudaFuncAttributeMaxDynamicSharedMemorySize,
                             ATT_SMEM_U32 * (int)sizeof(uint32_t));
        cudaFuncSetAttribute(gemm_f16_nt<0>,
                             cudaFuncAttributeMaxDynamicSharedMemorySize,
                             GEMM_SMEM_BYTES);
        cudaFuncSetAttribute(gemm_f16_nt<1>,
                             cudaFuncAttributeMaxDynamicSharedMemorySize,
                             GEMM_SMEM_BYTES);
        attr_set = true;
    }

    const int XBLK = (MROWS * DMODEL) / (256 * 4);   // 16384
    const int WBLK = (DMODEL * DMODEL) / (256 * 4);  // 1024
    cvt_f32_f16<<<XBLK, 256>>>(X,  Xh);
    cvt_f32_f16<<<WBLK, 256>>>(Wq, Wh0);
    cvt_f32_f16<<<WBLK, 256>>>(Wk, Wh1);
    cvt_f32_f16<<<WBLK, 256>>>(Wv, Wh2);
    cvt_f32_f16<<<WBLK, 256>>>(Wo, Wh3);

    dim3 gemm_grid(DMODEL / 128, MROWS / 128);   // (8, 128)
    gemm_f16_nt<0><<<gemm_grid, 128, GEMM_SMEM_BYTES>>>(Xh, Wh0, bq, Qp, MROWS, DMODEL, DMODEL);
    gemm_f16_nt<0><<<gemm_grid, 128, GEMM_SMEM_BYTES>>>(Xh, Wh1, bk, Kp, MROWS, DMODEL, DMODEL);
    gemm_f16_nt<0><<<gemm_grid, 128, GEMM_SMEM_BYTES>>>(Xh, Wh2, bv, Vp, MROWS, DMODEL, DMODEL);

    dim3 att_grid(SEQ / 128, NHEAD, BATCH);      // (8, 16, 16)
    attention_tc<<<att_grid, 128, ATT_SMEM_U32 * sizeof(uint32_t)>>>(Qp, Kp, Vp, Cp);

    gemm_f16_nt<1><<<gemm_grid, 128, GEMM_SMEM_BYTES>>>(Cp, Wh3, bo, out, MROWS, DMODEL, DMODEL);
}

// round 11
// speedup vs baseline: 7.0189x; 1.2323x over previous
#include <cuda_runtime.h>
#include <cuda_fp16.h>
#include <cstdint>
#include <math.h>

// ---------------------------------------------------------------------------
// AttentionActPrune: full MHA block. B=16, S=1024, d=1024, H=16, Dh=64.
// Round 11: fused QKV GEMM (N=3072), 4-stage single-barrier cp.async GEMM,
//           attention with double-buffered K/V (cp.async K, reg-prefetch V),
//           one barrier per iteration everywhere. fp16 m16n8k16 throughout.
// ---------------------------------------------------------------------------

#define BATCH   16
#define SEQ     1024
#define DMODEL  1024
#define NHEAD   16
#define DHEAD   64
#define MROWS   (BATCH * SEQ)          // 16384
#define NQKV    (3 * DMODEL)           // 3072

__device__ __half g_QKVh[(size_t)MROWS * NQKV];
__device__ __half g_Ch[(size_t)MROWS * DMODEL];
__device__ __half g_Xh[(size_t)MROWS * DMODEL];
__device__ __half g_Wh[4][(size_t)DMODEL * DMODEL];   // Wq,Wk,Wv,Wo contiguous
__device__ float  g_biasQKV[NQKV];

__device__ __forceinline__ void mma_fp16(float* c, uint32_t a0, uint32_t a1,
                                         uint32_t a2, uint32_t a3,
                                         uint32_t b0, uint32_t b1) {
    asm volatile(
        "mma.sync.aligned.m16n8k16.row.col.f32.f16.f16.f32 "
        "{%0,%1,%2,%3}, {%4,%5,%6,%7}, {%8,%9}, {%0,%1,%2,%3};"
        : "+f"(c[0]), "+f"(c[1]), "+f"(c[2]), "+f"(c[3])
        : "r"(a0), "r"(a1), "r"(a2), "r"(a3), "r"(b0), "r"(b1));
}

__device__ __forceinline__ uint32_t pack_h2(float lo, float hi) {
    __half2 h = __floats2half2_rn(lo, hi);
    return *(uint32_t*)&h;
}

__device__ __forceinline__ uint32_t smem_u32ptr(const void* p) {
    uint32_t a;
    asm("{ .reg .u64 t; cvta.to.shared.u64 t, %1; cvt.u32.u64 %0, t; }"
        : "=r"(a) : "l"(p));
    return a;
}

__device__ __forceinline__ void cp_async16(uint32_t s, const void* g) {
    asm volatile("cp.async.cg.shared.global [%0], [%1], 16;" :: "r"(s), "l"(g));
}
#define CP_COMMIT()  asm volatile("cp.async.commit_group;" ::: "memory")
#define CP_WAIT(n)   asm volatile("cp.async.wait_group %0;" :: "n"(n) : "memory")

// ---------------------------------------------------------------------------
// fp32 -> fp16 conversion pass
// ---------------------------------------------------------------------------
__global__ __launch_bounds__(256)
void cvt_f32_f16(const float* __restrict__ in, __half* __restrict__ out) {
    size_t i = ((size_t)blockIdx.x * 256 + threadIdx.x) * 4;
    float4 v = *(const float4*)(in + i);
    uint2 o = make_uint2(pack_h2(v.x, v.y), pack_h2(v.z, v.w));
    *(uint2*)(out + i) = o;
}

// ---------------------------------------------------------------------------
// fp16 GEMM (NT), 4-stage cp.async, single barrier/iter.
// 128 threads, 4 warps (2x2), warp tile 64x64 (mt=4, nt=8), BK=32.
// ---------------------------------------------------------------------------
#define GSTR 20
#define GST_U32    (128 * GSTR)        // 2560 u32 per matrix per stage
#define GSTAGE_U32 (2 * GST_U32)       // 5120 per stage (A then B)
#define GEMM_SMEM_BYTES (4 * GSTAGE_U32 * 4)   // 81920 B

template<int OUT32>
__global__ __launch_bounds__(128)
void gemm_f16_nt(const __half* __restrict__ A, const __half* __restrict__ B,
                 const float* __restrict__ bias, void* __restrict__ Cout,
                 int M, int N, int K)
{
    extern __shared__ uint32_t gsm[];
    const uint32_t smem_base = smem_u32ptr(gsm);

    const int tid  = threadIdx.x;
    const int wid  = tid >> 5;
    const int lane = tid & 31;
    const int g    = lane >> 2;
    const int tg   = lane & 3;
    const int warp_m = wid & 1;
    const int warp_n = wid >> 1;
    const int bm = blockIdx.y * 128;
    const int bn = blockIdx.x * 128;

    const int sr = tid >> 2;             // row base (advances +32 per i)
    const int sc = tid & 3;              // 16B chunk (8 halves)

    auto issue_stage = [&](int stage, int k0) {
        const uint32_t sa = smem_base + (uint32_t)stage * GSTAGE_U32 * 4;
        const uint32_t sb = sa + GST_U32 * 4;
#pragma unroll
        for (int i = 0; i < 4; i++) {
            const int r = sr + i * 32;
            const uint32_t off = (uint32_t)(r * GSTR + sc * 4) * 4;
            cp_async16(sa + off, A + (size_t)(bm + r) * K + k0 + sc * 8);
            cp_async16(sb + off, B + (size_t)(bn + r) * K + k0 + sc * 8);
        }
        CP_COMMIT();
    };

    const int nkc = K / 32;              // 32
    issue_stage(0, 0);
    issue_stage(1, 32);

    float acc[4][8][4];
#pragma unroll
    for (int i = 0; i < 4; i++)
#pragma unroll
        for (int j = 0; j < 8; j++)
#pragma unroll
            for (int q = 0; q < 4; q++) acc[i][j][q] = 0.f;

    for (int kc = 0; kc < nkc; kc++) {
        if (kc + 2 < nkc) issue_stage((kc + 2) & 3, (kc + 2) * 32);
        else              CP_COMMIT();   // empty group keeps wait count uniform
        CP_WAIT(2);                      // chunk kc arrived (own groups)
        __syncthreads();                 // all warps' copies visible

        const uint32_t* bufA = gsm + (kc & 3) * GSTAGE_U32;
        const uint32_t* bufB = bufA + GST_U32;

#pragma unroll
        for (int ks = 0; ks < 2; ks++) {
            const int kcol = ks * 8 + 2 * tg;
            uint2 aLo[4], aHi[4];
#pragma unroll
            for (int mt = 0; mt < 4; mt++) {
                int r = warp_m * 64 + mt * 16 + g;
                aLo[mt] = *(const uint2*)&bufA[r * GSTR + kcol];
                aHi[mt] = *(const uint2*)&bufA[(r + 8) * GSTR + kcol];
            }
            uint2 bf[8];
#pragma unroll
            for (int nt = 0; nt < 8; nt++) {
                int rn = warp_n * 64 + nt * 8 + g;
                bf[nt] = *(const uint2*)&bufB[rn * GSTR + kcol];
            }
#pragma unroll
            for (int mt = 0; mt < 4; mt++)
#pragma unroll
                for (int nt = 0; nt < 8; nt++)
                    mma_fp16(acc[mt][nt],
                             aLo[mt].x, aHi[mt].x, aLo[mt].y, aHi[mt].y,
                             bf[nt].x, bf[nt].y);
        }
        // single barrier per iter: the next iteration's barrier (after its
        // wait) provides the collective point; overwrite target at iter j is
        // chunk j-2's buffer, whose reads finished before BAR(j-1).
    }

#pragma unroll
    for (int mt = 0; mt < 4; mt++) {
        const int row0 = bm + warp_m * 64 + mt * 16 + g;
#pragma unroll
        for (int nt = 0; nt < 8; nt++) {
            const int col = bn + warp_n * 64 + nt * 8 + 2 * tg;
            const float b0 = bias[col], b1 = bias[col + 1];
            if (OUT32) {
                float* C = (float*)Cout;
                *(float2*)(C + (size_t)row0 * N + col) =
                    make_float2(acc[mt][nt][0] + b0, acc[mt][nt][1] + b1);
                *(float2*)(C + (size_t)(row0 + 8) * N + col) =
                    make_float2(acc[mt][nt][2] + b0, acc[mt][nt][3] + b1);
            } else {
                __half* C = (__half*)Cout;
                *(uint32_t*)(C + (size_t)row0 * N + col) =
                    pack_h2(acc[mt][nt][0] + b0, acc[mt][nt][1] + b1);
                *(uint32_t*)(C + (size_t)(row0 + 8) * N + col) =
                    pack_h2(acc[mt][nt][2] + b0, acc[mt][nt][3] + b1);
            }
        }
    }
}

// ---------------------------------------------------------------------------
// fp16 flash attention, double-buffered K/V, one barrier/iter.
// Q/K/V read from concatenated QKV buffer (row stride NQKV).
// K staged via raw cp.async (stride 44 u32: 16B-aligned rows).
// V prefetched to registers during compute, STS'd into alternate buffer.
// ---------------------------------------------------------------------------
#define QSTR 42
#define KSTR 44
#define VSTR 42
#define Q_U32 (128 * QSTR)             // 5376
#define K_U32 (64 * KSTR)              // 2816 per buffer
#define V_U32 (64 * VSTR)              // 2688 per buffer
#define ATT_SMEM_U32 (Q_U32 + 2 * K_U32 + 2 * V_U32)   // 16384 u32 = 65536 B

__global__ __launch_bounds__(128, 2)
void attention_tc(const __half* __restrict__ QKV, __half* __restrict__ C)
{
    extern __shared__ uint32_t sm[];
    uint32_t* Qs = sm;                          // Q, natural, stride 42
    uint32_t* Ks = sm + Q_U32;                  // 2 buffers, stride 44
    uint32_t* Vt = Ks + 2 * K_U32;              // 2 buffers, d-major pairs
    const uint32_t smem_base = smem_u32ptr(sm);
    const uint32_t ks_base_b = smem_base + Q_U32 * 4;

    const int tid  = threadIdx.x;
    const int wid  = tid >> 5;
    const int lane = tid & 31;
    const int g    = lane >> 2;
    const int tg   = lane & 3;
    const int qb = blockIdx.x;
    const int h  = blockIdx.y;
    const int b  = blockIdx.z;
    const size_t baseQ = (size_t)b * SEQ * NQKV + h * DHEAD;
    const size_t baseK = baseQ + DMODEL;
    const size_t baseV = baseQ + 2 * DMODEL;
    const size_t baseC = (size_t)b * SEQ * DMODEL + h * DHEAD;
    const int wr = wid * 32;

    const __half2 hscale = __floats2half2_rn(0.125f, 0.125f);

    // K cp.async staging coords: 512 16B-chunks, 4 per thread
    const int kr = tid >> 3;             // key base (advances +16 per i)
    const int kcnk = tid & 7;            // 16B chunk within row

    auto issue_K = [&](int kb, int buf) {
        const uint32_t kd = ks_base_b + (uint32_t)buf * K_U32 * 4;
#pragma unroll
        for (int i = 0; i < 4; i++) {
            const int key = kr + i * 16;
            cp_async16(kd + (uint32_t)(key * KSTR + kcnk * 4) * 4,
                       QKV + baseK + (size_t)(kb * 64 + key) * NQKV + kcnk * 8);
        }
        CP_COMMIT();
    };

    // V prefetch coords (4 tasks/thread)
    const int vp_p  = tid >> 4;          // key-pair base (advances +8 per i)
    const int vp_dc = tid & 15;          // 4-d chunk

    auto ldg_V = [&](int kb, uint2* ea, uint2* eb) {
#pragma unroll
        for (int i = 0; i < 4; i++) {
            const int p = vp_p + i * 8;
            const __half* vb = QKV + baseV + (size_t)(kb * 64 + 2 * p) * NQKV + vp_dc * 4;
            ea[i] = *(const uint2*)(vb);
            eb[i] = *(const uint2*)(vb + NQKV);
        }
    };
    auto sts_V = [&](int buf, const uint2* ea, const uint2* eb) {
        uint32_t* vd = Vt + buf * V_U32;
#pragma unroll
        for (int i = 0; i < 4; i++) {
            const int p = vp_p + i * 8;
            __half2 ax = *(__half2*)&ea[i].x, ay = *(__half2*)&ea[i].y;
            __half2 bx = *(__half2*)&eb[i].x, by = *(__half2*)&eb[i].y;
            int pos = (p & ~7) + 2 * (p & 3) + ((p >> 2) & 1);
            __half2 o0 = __lows2half2(ax, bx), o1 = __highs2half2(ax, bx);
            __half2 o2 = __lows2half2(ay, by), o3 = __highs2half2(ay, by);
            vd[(vp_dc * 4 + 0) * VSTR + pos] = *(uint32_t*)&o0;
            vd[(vp_dc * 4 + 1) * VSTR + pos] = *(uint32_t*)&o1;
            vd[(vp_dc * 4 + 2) * VSTR + pos] = *(uint32_t*)&o2;
            vd[(vp_dc * 4 + 3) * VSTR + pos] = *(uint32_t*)&o3;
        }
    };

    // ---- prologue: stage Q (scaled), issue K0, prefetch+store V0 ----
    issue_K(0, 0);
    {
        uint2 ea[4], eb[4];
        ldg_V(0, ea, eb);
        sts_V(0, ea, eb);
    }
#pragma unroll
    for (int i = 0; i < 16; i++) {
        int t = tid + i * 128;
        int r = t >> 4, c = t & 15;
        uint2 v = *(const uint2*)(QKV + baseQ + (size_t)(qb * 128 + r) * NQKV + c * 4);
        __half2 a = __hmul2(*(__half2*)&v.x, hscale);
        __half2 bb = __hmul2(*(__half2*)&v.y, hscale);
        Qs[r * QSTR + c * 2 + 0] = *(uint32_t*)&a;
        Qs[r * QSTR + c * 2 + 1] = *(uint32_t*)&bb;
    }
    CP_WAIT(0);
    __syncthreads();

    // ---- hoist Q fragments ----
    uint2 qLo[2][4], qHi[2][4];
#pragma unroll
    for (int ks = 0; ks < 4; ks++) {
        const int kcol = ks * 8 + 2 * tg;
#pragma unroll
        for (int mt = 0; mt < 2; mt++) {
            qLo[mt][ks] = *(const uint2*)&Qs[(wr + mt * 16 + g) * QSTR + kcol];
            qHi[mt][ks] = *(const uint2*)&Qs[(wr + mt * 16 + g + 8) * QSTR + kcol];
        }
    }

    float o[2][8][4];
#pragma unroll
    for (int mt = 0; mt < 2; mt++)
#pragma unroll
        for (int nt = 0; nt < 8; nt++)
#pragma unroll
            for (int q = 0; q < 4; q++) o[mt][nt][q] = 0.f;
    float mrow[2][2], lrow[2][2];
#pragma unroll
    for (int mt = 0; mt < 2; mt++) {
        mrow[mt][0] = mrow[mt][1] = -1e30f;
        lrow[mt][0] = lrow[mt][1] = 0.f;
    }

    for (int kb = 0; kb < SEQ / 64; kb++) {
        const int nb = (kb + 1) & 1;
        const bool more = (kb + 1 < SEQ / 64);
        // issue next K copy + prefetch next V (latency hidden by compute)
        if (more) issue_K(kb + 1, nb);
        else      CP_COMMIT();
        uint2 ea[4], eb[4];
        ldg_V(more ? kb + 1 : kb, ea, eb);

        const uint32_t* Kb = Ks + (kb & 1) * K_U32;
        const uint32_t* Vb = Vt + (kb & 1) * V_U32;

        // ---- S = Q @ K^T ----
        float s[2][8][4];
#pragma unroll
        for (int mt = 0; mt < 2; mt++)
#pragma unroll
            for (int nt = 0; nt < 8; nt++)
#pragma unroll
                for (int q = 0; q < 4; q++) s[mt][nt][q] = 0.f;

#pragma unroll
        for (int ks = 0; ks < 4; ks++) {
            const int kcol = ks * 8 + 2 * tg;
#pragma unroll
            for (int nt = 0; nt < 8; nt++) {
                uint2 bf = *(const uint2*)&Kb[(nt * 8 + g) * KSTR + kcol];
#pragma unroll
                for (int mt = 0; mt < 2; mt++)
                    mma_fp16(s[mt][nt],
                             qLo[mt][ks].x, qHi[mt][ks].x,
                             qLo[mt][ks].y, qHi[mt][ks].y,
                             bf.x, bf.y);
            }
        }

        // ---- online softmax; P packed to half2 in registers ----
        uint32_t ph[2][8][2];
#pragma unroll
        for (int mt = 0; mt < 2; mt++) {
            float mx0 = -1e30f, mx1 = -1e30f;
#pragma unroll
            for (int nt = 0; nt < 8; nt++) {
                mx0 = fmaxf(mx0, fmaxf(s[mt][nt][0], s[mt][nt][1]));
                mx1 = fmaxf(mx1, fmaxf(s[mt][nt][2], s[mt][nt][3]));
            }
            mx0 = fmaxf(mx0, __shfl_xor_sync(0xffffffffu, mx0, 1));
            mx0 = fmaxf(mx0, __shfl_xor_sync(0xffffffffu, mx0, 2));
            mx1 = fmaxf(mx1, __shfl_xor_sync(0xffffffffu, mx1, 1));
            mx1 = fmaxf(mx1, __shfl_xor_sync(0xffffffffu, mx1, 2));
            const float mn0 = fmaxf(mrow[mt][0], mx0);
            const float mn1 = fmaxf(mrow[mt][1], mx1);
            const float al0 = __expf(mrow[mt][0] - mn0);
            const float al1 = __expf(mrow[mt][1] - mn1);
            mrow[mt][0] = mn0; mrow[mt][1] = mn1;

            float sum0 = 0.f, sum1 = 0.f;
#pragma unroll
            for (int nt = 0; nt < 8; nt++) {
                float p0 = __expf(s[mt][nt][0] - mn0);
                float p1 = __expf(s[mt][nt][1] - mn0);
                float p2 = __expf(s[mt][nt][2] - mn1);
                float p3 = __expf(s[mt][nt][3] - mn1);
                sum0 += p0 + p1; sum1 += p2 + p3;
                ph[mt][nt][0] = pack_h2(p0, p1);
                ph[mt][nt][1] = pack_h2(p2, p3);
                o[mt][nt][0] *= al0; o[mt][nt][1] *= al0;
                o[mt][nt][2] *= al1; o[mt][nt][3] *= al1;
            }
            sum0 += __shfl_xor_sync(0xffffffffu, sum0, 1);
            sum0 += __shfl_xor_sync(0xffffffffu, sum0, 2);
            sum1 += __shfl_xor_sync(0xffffffffu, sum1, 1);
            sum1 += __shfl_xor_sync(0xffffffffu, sum1, 2);
            lrow[mt][0] = lrow[mt][0] * al0 + sum0;
            lrow[mt][1] = lrow[mt][1] * al1 + sum1;
        }

        // ---- O += P @ V ----
#pragma unroll
        for (int kc = 0; kc < 4; kc++) {
            const int vcol = kc * 8 + 2 * tg;
#pragma unroll
            for (int nt = 0; nt < 8; nt++) {
                uint2 bf = *(const uint2*)&Vb[(nt * 8 + g) * VSTR + vcol];
#pragma unroll
                for (int mt = 0; mt < 2; mt++)
                    mma_fp16(o[mt][nt],
                             ph[mt][2 * kc][0], ph[mt][2 * kc][1],
                             ph[mt][2 * kc + 1][0], ph[mt][2 * kc + 1][1],
                             bf.x, bf.y);
            }
        }

        // store prefetched V into the OTHER buffer, then the single barrier
        if (more) sts_V(nb, ea, eb);
        CP_WAIT(0);
        __syncthreads();
    }

    // ---- normalize + store ctx (half) ----
#pragma unroll
    for (int mt = 0; mt < 2; mt++) {
        const float li0 = 1.f / lrow[mt][0];
        const float li1 = 1.f / lrow[mt][1];
        const size_t r0 = baseC + (size_t)(qb * 128 + wr + mt * 16 + g) * DMODEL;
        const size_t r1 = r0 + (size_t)8 * DMODEL;
#pragma unroll
        for (int nt = 0; nt < 8; nt++) {
            const int col = nt * 8 + 2 * tg;
            *(uint32_t*)(C + r0 + col) = pack_h2(o[mt][nt][0] * li0, o[mt][nt][1] * li0);
            *(uint32_t*)(C + r1 + col) = pack_h2(o[mt][nt][2] * li1, o[mt][nt][3] * li1);
        }
    }
}

// ---------------------------------------------------------------------------
// Launch
// ---------------------------------------------------------------------------
extern "C" void kernel_launch(void* const* d_in, const int* in_sizes, int n_in,
                              void* d_out, int out_size)
{
    const float* X  = (const float*)d_in[0];
    const float* Wq = (const float*)d_in[1];
    const float* bq = (const float*)d_in[2];
    const float* Wk = (const float*)d_in[3];
    const float* bk = (const float*)d_in[4];
    const float* Wv = (const float*)d_in[5];
    const float* bv = (const float*)d_in[6];
    const float* Wo = (const float*)d_in[7];
    const float* bo = (const float*)d_in[8];
    float* out = (float*)d_out;

    __half *QKVp, *Cp, *Xh, *Wh;
    float* biasQKV;
    cudaGetSymbolAddress((void**)&QKVp, g_QKVh);
    cudaGetSymbolAddress((void**)&Cp, g_Ch);
    cudaGetSymbolAddress((void**)&Xh, g_Xh);
    cudaGetSymbolAddress((void**)&Wh, g_Wh);
    cudaGetSymbolAddress((void**)&biasQKV, g_biasQKV);
    __half* Wh0 = Wh;
    __half* Wh3 = Wh + 3 * (size_t)DMODEL * DMODEL;

    static bool attr_set = false;
    if (!attr_set) {
        cudaFuncSetAttribute(attention_tc,
                             cudaFuncAttributeMaxDynamicSharedMemorySize,
                             ATT_SMEM_U32 * (int)sizeof(uint32_t));
        cudaFuncSetAttribute(gemm_f16_nt<0>,
                             cudaFuncAttributeMaxDynamicSharedMemorySize,
                             GEMM_SMEM_BYTES);
        cudaFuncSetAttribute(gemm_f16_nt<1>,
                             cudaFuncAttributeMaxDynamicSharedMemorySize,
                             GEMM_SMEM_BYTES);
        attr_set = true;
    }

    // concatenated QKV bias (async D2D copies are graph-capturable)
    cudaMemcpyAsync(biasQKV,          bq, DMODEL * sizeof(float), cudaMemcpyDeviceToDevice);
    cudaMemcpyAsync(biasQKV + DMODEL, bk, DMODEL * sizeof(float), cudaMemcpyDeviceToDevice);
    cudaMemcpyAsync(biasQKV + 2*DMODEL, bv, DMODEL * sizeof(float), cudaMemcpyDeviceToDevice);

    const int XBLK = (MROWS * DMODEL) / (256 * 4);   // 16384
    const int WBLK = (DMODEL * DMODEL) / (256 * 4);  // 1024
    cvt_f32_f16<<<XBLK, 256>>>(X,  Xh);
    cvt_f32_f16<<<WBLK, 256>>>(Wq, Wh0);
    cvt_f32_f16<<<WBLK, 256>>>(Wk, Wh0 + (size_t)DMODEL * DMODEL);
    cvt_f32_f16<<<WBLK, 256>>>(Wv, Wh0 + 2 * (size_t)DMODEL * DMODEL);
    cvt_f32_f16<<<WBLK, 256>>>(Wo, Wh3);

    // fused QKV projection: N = 3072 (weights contiguous)
    dim3 qkv_grid(NQKV / 128, MROWS / 128);      // (24, 128)
    gemm_f16_nt<0><<<qkv_grid, 128, GEMM_SMEM_BYTES>>>(
        Xh, Wh0, biasQKV, QKVp, MROWS, NQKV, DMODEL);

    dim3 att_grid(SEQ / 128, NHEAD, BATCH);      // (8, 16, 16)
    attention_tc<<<att_grid, 128, ATT_SMEM_U32 * sizeof(uint32_t)>>>(QKVp, Cp);

    dim3 o_grid(DMODEL / 128, MROWS / 128);      // (8, 128)
    gemm_f16_nt<1><<<o_grid, 128, GEMM_SMEM_BYTES>>>(
        Cp, Wh3, bo, out, MROWS, DMODEL, DMODEL);
}

// round 13
// speedup vs baseline: 7.4442x; 1.0606x over previous
#include <cuda_runtime.h>
#include <cuda_fp16.h>
#include <cstdint>
#include <math.h>

// ---------------------------------------------------------------------------
// AttentionActPrune: full MHA block. B=16, S=1024, d=1024, H=16, Dh=64.
// Round 13: R12 with the LDSM alignment fix (QSTR 42 -> 44: ldmatrix needs
//           16B-aligned row pointers; 42 u32 = 168 B rows trapped).
//           LDSM.x4 fragment loads in GEMM (A+B) and attention (Q + K).
// ---------------------------------------------------------------------------

#define BATCH   16
#define SEQ     1024
#define DMODEL  1024
#define NHEAD   16
#define DHEAD   64
#define MROWS   (BATCH * SEQ)          // 16384
#define NQKV    (3 * DMODEL)           // 3072

__device__ __half g_QKVh[(size_t)MROWS * NQKV];
__device__ __half g_Ch[(size_t)MROWS * DMODEL];
__device__ __half g_Xh[(size_t)MROWS * DMODEL];
__device__ __half g_Wh[4][(size_t)DMODEL * DMODEL];
__device__ float  g_biasQKV[NQKV];

__device__ __forceinline__ void mma_fp16(float* c, uint32_t a0, uint32_t a1,
                                         uint32_t a2, uint32_t a3,
                                         uint32_t b0, uint32_t b1) {
    asm volatile(
        "mma.sync.aligned.m16n8k16.row.col.f32.f16.f16.f32 "
        "{%0,%1,%2,%3}, {%4,%5,%6,%7}, {%8,%9}, {%0,%1,%2,%3};"
        : "+f"(c[0]), "+f"(c[1]), "+f"(c[2]), "+f"(c[3])
        : "r"(a0), "r"(a1), "r"(a2), "r"(a3), "r"(b0), "r"(b1));
}

__device__ __forceinline__ void ldsm_x4(uint32_t& r0, uint32_t& r1,
                                        uint32_t& r2, uint32_t& r3,
                                        uint32_t addr) {
    asm volatile("ldmatrix.sync.aligned.m8n8.x4.shared.b16 {%0,%1,%2,%3}, [%4];"
                 : "=r"(r0), "=r"(r1), "=r"(r2), "=r"(r3) : "r"(addr));
}

__device__ __forceinline__ uint32_t pack_h2(float lo, float hi) {
    __half2 h = __floats2half2_rn(lo, hi);
    return *(uint32_t*)&h;
}

__device__ __forceinline__ uint32_t smem_u32ptr(const void* p) {
    uint32_t a;
    asm("{ .reg .u64 t; cvta.to.shared.u64 t, %1; cvt.u32.u64 %0, t; }"
        : "=r"(a) : "l"(p));
    return a;
}

__device__ __forceinline__ void cp_async16(uint32_t s, const void* g) {
    asm volatile("cp.async.cg.shared.global [%0], [%1], 16;" :: "r"(s), "l"(g));
}
#define CP_COMMIT()  asm volatile("cp.async.commit_group;" ::: "memory")
#define CP_WAIT(n)   asm volatile("cp.async.wait_group %0;" :: "n"(n) : "memory")

// ---------------------------------------------------------------------------
// fp32 -> fp16 conversion pass
// ---------------------------------------------------------------------------
__global__ __launch_bounds__(256)
void cvt_f32_f16(const float* __restrict__ in, __half* __restrict__ out) {
    size_t i = ((size_t)blockIdx.x * 256 + threadIdx.x) * 4;
    float4 v = *(const float4*)(in + i);
    uint2 o = make_uint2(pack_h2(v.x, v.y), pack_h2(v.z, v.w));
    *(uint2*)(out + i) = o;
}

// ---------------------------------------------------------------------------
// fp16 GEMM (NT), 4-stage cp.async + LDSM fragments, single barrier/iter.
// 128 threads, 4 warps (2x2), warp tile 64x64 (mt=4, nt=8), BK=32.
// GSTR=20 u32 (80 B rows = 5x16: LDSM-aligned; row-start banks 20r distinct).
// ---------------------------------------------------------------------------
#define GSTR 20
#define GST_U32    (128 * GSTR)
#define GSTAGE_U32 (2 * GST_U32)
#define GEMM_SMEM_BYTES (4 * GSTAGE_U32 * 4)   // 81920 B

template<int OUT32>
__global__ __launch_bounds__(128)
void gemm_f16_nt(const __half* __restrict__ A, const __half* __restrict__ B,
                 const float* __restrict__ bias, void* __restrict__ Cout,
                 int M, int N, int K)
{
    extern __shared__ uint32_t gsm[];
    const uint32_t smem_base = smem_u32ptr(gsm);

    const int tid  = threadIdx.x;
    const int wid  = tid >> 5;
    const int lane = tid & 31;
    const int g    = lane >> 2;
    const int tg   = lane & 3;
    const int warp_m = wid & 1;
    const int warp_n = wid >> 1;
    const int bm = blockIdx.y * 128;
    const int bn = blockIdx.x * 128;

    const int sr = tid >> 2;
    const int sc = tid & 3;

    auto issue_stage = [&](int stage, int k0) {
        const uint32_t sa = smem_base + (uint32_t)stage * GSTAGE_U32 * 4;
        const uint32_t sb = sa + GST_U32 * 4;
#pragma unroll
        for (int i = 0; i < 4; i++) {
            const int r = sr + i * 32;
            const uint32_t off = (uint32_t)(r * GSTR + sc * 4) * 4;
            cp_async16(sa + off, A + (size_t)(bm + r) * K + k0 + sc * 8);
            cp_async16(sb + off, B + (size_t)(bn + r) * K + k0 + sc * 8);
        }
        CP_COMMIT();
    };

    // LDSM per-lane base offsets (bytes, relative to stage A/B base)
    const uint32_t a_lane_off =
        (uint32_t)((warp_m * 64 + (lane & 15)) * GSTR) * 4 + (lane >> 4) * 16;
    const uint32_t b_lane_off =
        (uint32_t)((warp_n * 64 + (lane & 7) + ((lane & 16) ? 8 : 0)) * GSTR) * 4
        + ((lane >> 3) & 1) * 16;

    const int nkc = K / 32;
    issue_stage(0, 0);
    issue_stage(1, 32);

    float acc[4][8][4];
#pragma unroll
    for (int i = 0; i < 4; i++)
#pragma unroll
        for (int j = 0; j < 8; j++)
#pragma unroll
            for (int q = 0; q < 4; q++) acc[i][j][q] = 0.f;

    for (int kc = 0; kc < nkc; kc++) {
        if (kc + 2 < nkc) issue_stage((kc + 2) & 3, (kc + 2) * 32);
        else              CP_COMMIT();
        CP_WAIT(2);
        __syncthreads();

        const uint32_t stA = smem_base + (uint32_t)(kc & 3) * GSTAGE_U32 * 4;
        const uint32_t stB = stA + GST_U32 * 4;

#pragma unroll
        for (int ks = 0; ks < 2; ks++) {
            uint32_t af[4][4];
#pragma unroll
            for (int mt = 0; mt < 4; mt++)
                ldsm_x4(af[mt][0], af[mt][1], af[mt][2], af[mt][3],
                        stA + a_lane_off + (uint32_t)(mt * 16 * GSTR) * 4 + ks * 32);
            uint32_t bfr[4][4];
#pragma unroll
            for (int j = 0; j < 4; j++)
                ldsm_x4(bfr[j][0], bfr[j][1], bfr[j][2], bfr[j][3],
                        stB + b_lane_off + (uint32_t)(j * 16 * GSTR) * 4 + ks * 32);
#pragma unroll
            for (int mt = 0; mt < 4; mt++)
#pragma unroll
                for (int nt = 0; nt < 8; nt++)
                    mma_fp16(acc[mt][nt],
                             af[mt][0], af[mt][1], af[mt][2], af[mt][3],
                             bfr[nt >> 1][(nt & 1) * 2],
                             bfr[nt >> 1][(nt & 1) * 2 + 1]);
        }
    }

#pragma unroll
    for (int mt = 0; mt < 4; mt++) {
        const int row0 = bm + warp_m * 64 + mt * 16 + g;
#pragma unroll
        for (int nt = 0; nt < 8; nt++) {
            const int col = bn + warp_n * 64 + nt * 8 + 2 * tg;
            const float b0 = bias[col], b1 = bias[col + 1];
            if (OUT32) {
                float* C = (float*)Cout;
                *(float2*)(C + (size_t)row0 * N + col) =
                    make_float2(acc[mt][nt][0] + b0, acc[mt][nt][1] + b1);
                *(float2*)(C + (size_t)(row0 + 8) * N + col) =
                    make_float2(acc[mt][nt][2] + b0, acc[mt][nt][3] + b1);
            } else {
                __half* C = (__half*)Cout;
                *(uint32_t*)(C + (size_t)row0 * N + col) =
                    pack_h2(acc[mt][nt][0] + b0, acc[mt][nt][1] + b1);
                *(uint32_t*)(C + (size_t)(row0 + 8) * N + col) =
                    pack_h2(acc[mt][nt][2] + b0, acc[mt][nt][3] + b1);
            }
        }
    }
}

// ---------------------------------------------------------------------------
// fp16 flash attention, double-buffered K/V, one barrier/iter.
// Q hoist + K fragments via LDSM. QSTR=44 (176 B rows = 11x16: LDSM-aligned,
// banks 12r distinct). KSTR=44 likewise. PV keeps register-P layout.
// ---------------------------------------------------------------------------
#define QSTR 44
#define KSTR 44
#define VSTR 42
#define Q_U32 (128 * QSTR)             // 5632
#define K_U32 (64 * KSTR)              // 2816 per buffer
#define V_U32 (64 * VSTR)              // 2688 per buffer
#define ATT_SMEM_U32 (Q_U32 + 2 * K_U32 + 2 * V_U32)   // 16640 u32 = 66560 B

__global__ __launch_bounds__(128, 2)
void attention_tc(const __half* __restrict__ QKV, __half* __restrict__ C)
{
    extern __shared__ uint32_t sm[];
    uint32_t* Qs = sm;
    uint32_t* Vt = sm + Q_U32 + 2 * K_U32;
    const uint32_t smem_base = smem_u32ptr(sm);
    const uint32_t ks_base_b = smem_base + Q_U32 * 4;

    const int tid  = threadIdx.x;
    const int wid  = tid >> 5;
    const int lane = tid & 31;
    const int g    = lane >> 2;
    const int tg   = lane & 3;
    const int qb = blockIdx.x;
    const int h  = blockIdx.y;
    const int b  = blockIdx.z;
    const size_t baseQ = (size_t)b * SEQ * NQKV + h * DHEAD;
    const size_t baseK = baseQ + DMODEL;
    const size_t baseV = baseQ + 2 * DMODEL;
    const size_t baseC = (size_t)b * SEQ * DMODEL + h * DHEAD;
    const int wr = wid * 32;

    const __half2 hscale = __floats2half2_rn(0.125f, 0.125f);

    const int kr = tid >> 3;
    const int kcnk = tid & 7;
    auto issue_K = [&](int kb, int buf) {
        const uint32_t kd = ks_base_b + (uint32_t)buf * K_U32 * 4;
#pragma unroll
        for (int i = 0; i < 4; i++) {
            const int key = kr + i * 16;
            cp_async16(kd + (uint32_t)(key * KSTR + kcnk * 4) * 4,
                       QKV + baseK + (size_t)(kb * 64 + key) * NQKV + kcnk * 8);
        }
        CP_COMMIT();
    };

    const int vp_p  = tid >> 4;
    const int vp_dc = tid & 15;
    auto ldg_V = [&](int kb, uint2* ea, uint2* eb) {
#pragma unroll
        for (int i = 0; i < 4; i++) {
            const int p = vp_p + i * 8;
            const __half* vb = QKV + baseV + (size_t)(kb * 64 + 2 * p) * NQKV + vp_dc * 4;
            ea[i] = *(const uint2*)(vb);
            eb[i] = *(const uint2*)(vb + NQKV);
        }
    };
    auto sts_V = [&](int buf, const uint2* ea, const uint2* eb) {
        uint32_t* vd = Vt + buf * V_U32;
#pragma unroll
        for (int i = 0; i < 4; i++) {
            const int p = vp_p + i * 8;
            __half2 ax = *(__half2*)&ea[i].x, ay = *(__half2*)&ea[i].y;
            __half2 bx = *(__half2*)&eb[i].x, by = *(__half2*)&eb[i].y;
            int pos = (p & ~7) + 2 * (p & 3) + ((p >> 2) & 1);
            __half2 o0 = __lows2half2(ax, bx), o1 = __highs2half2(ax, bx);
            __half2 o2 = __lows2half2(ay, by), o3 = __highs2half2(ay, by);
            vd[(vp_dc * 4 + 0) * VSTR + pos] = *(uint32_t*)&o0;
            vd[(vp_dc * 4 + 1) * VSTR + pos] = *(uint32_t*)&o1;
            vd[(vp_dc * 4 + 2) * VSTR + pos] = *(uint32_t*)&o2;
            vd[(vp_dc * 4 + 3) * VSTR + pos] = *(uint32_t*)&o3;
        }
    };

    // ---- prologue: issue K0, stage V0, stage Q (scaled) ----
    issue_K(0, 0);
    {
        uint2 ea[4], eb[4];
        ldg_V(0, ea, eb);
        sts_V(0, ea, eb);
    }
#pragma unroll
    for (int i = 0; i < 16; i++) {
        int t = tid + i * 128;
        int r = t >> 4, c = t & 15;
        uint2 v = *(const uint2*)(QKV + baseQ + (size_t)(qb * 128 + r) * NQKV + c * 4);
        __half2 a = __hmul2(*(__half2*)&v.x, hscale);
        __half2 bb = __hmul2(*(__half2*)&v.y, hscale);
        Qs[r * QSTR + c * 2 + 0] = *(uint32_t*)&a;
        Qs[r * QSTR + c * 2 + 1] = *(uint32_t*)&bb;
    }
    CP_WAIT(0);
    __syncthreads();

    // ---- hoist Q fragments via LDSM (canonical a0..a3) ----
    const uint32_t q_lane_off =
        (uint32_t)((wr + (lane & 15)) * QSTR) * 4 + (lane >> 4) * 16;
    uint32_t qf[2][4][4];
#pragma unroll
    for (int mt = 0; mt < 2; mt++)
#pragma unroll
        for (int ks = 0; ks < 4; ks++)
            ldsm_x4(qf[mt][ks][0], qf[mt][ks][1], qf[mt][ks][2], qf[mt][ks][3],
                    smem_base + q_lane_off + (uint32_t)(mt * 16 * QSTR) * 4 + ks * 32);

    // K LDSM per-lane base (relative to K buffer base, bytes)
    const uint32_t k_lane_off =
        (uint32_t)(((lane & 7) + ((lane & 16) ? 8 : 0)) * KSTR) * 4
        + ((lane >> 3) & 1) * 16;

    float o[2][8][4];
#pragma unroll
    for (int mt = 0; mt < 2; mt++)
#pragma unroll
        for (int nt = 0; nt < 8; nt++)
#pragma unroll
            for (int q = 0; q < 4; q++) o[mt][nt][q] = 0.f;
    float mrow[2][2], lrow[2][2];
#pragma unroll
    for (int mt = 0; mt < 2; mt++) {
        mrow[mt][0] = mrow[mt][1] = -1e30f;
        lrow[mt][0] = lrow[mt][1] = 0.f;
    }

    for (int kb = 0; kb < SEQ / 64; kb++) {
        const int nb = (kb + 1) & 1;
        const bool more = (kb + 1 < SEQ / 64);
        if (more) issue_K(kb + 1, nb);
        else      CP_COMMIT();
        uint2 ea[4], eb[4];
        ldg_V(more ? kb + 1 : kb, ea, eb);

        const uint32_t kbuf = ks_base_b + (uint32_t)(kb & 1) * K_U32 * 4;
        const uint32_t* Vb = Vt + (kb & 1) * V_U32;

        // ---- S = Q @ K^T (LDSM K fragments, 2 nt per x4) ----
        float s[2][8][4];
#pragma unroll
        for (int mt = 0; mt < 2; mt++)
#pragma unroll
            for (int nt = 0; nt < 8; nt++)
#pragma unroll
                for (int q = 0; q < 4; q++) s[mt][nt][q] = 0.f;

#pragma unroll
        for (int ks = 0; ks < 4; ks++) {
            uint32_t kf[4][4];
#pragma unroll
            for (int j = 0; j < 4; j++)
                ldsm_x4(kf[j][0], kf[j][1], kf[j][2], kf[j][3],
                        kbuf + k_lane_off + (uint32_t)(j * 16 * KSTR) * 4 + ks * 32);
#pragma unroll
            for (int nt = 0; nt < 8; nt++)
#pragma unroll
                for (int mt = 0; mt < 2; mt++)
                    mma_fp16(s[mt][nt],
                             qf[mt][ks][0], qf[mt][ks][1],
                             qf[mt][ks][2], qf[mt][ks][3],
                             kf[nt >> 1][(nt & 1) * 2],
                             kf[nt >> 1][(nt & 1) * 2 + 1]);
        }

        // ---- online softmax; P packed to half2 in registers ----
        uint32_t ph[2][8][2];
#pragma unroll
        for (int mt = 0; mt < 2; mt++) {
            float mx0 = -1e30f, mx1 = -1e30f;
#pragma unroll
            for (int nt = 0; nt < 8; nt++) {
                mx0 = fmaxf(mx0, fmaxf(s[mt][nt][0], s[mt][nt][1]));
                mx1 = fmaxf(mx1, fmaxf(s[mt][nt][2], s[mt][nt][3]));
            }
            mx0 = fmaxf(mx0, __shfl_xor_sync(0xffffffffu, mx0, 1));
            mx0 = fmaxf(mx0, __shfl_xor_sync(0xffffffffu, mx0, 2));
            mx1 = fmaxf(mx1, __shfl_xor_sync(0xffffffffu, mx1, 1));
            mx1 = fmaxf(mx1, __shfl_xor_sync(0xffffffffu, mx1, 2));
            const float mn0 = fmaxf(mrow[mt][0], mx0);
            const float mn1 = fmaxf(mrow[mt][1], mx1);
            const float al0 = __expf(mrow[mt][0] - mn0);
            const float al1 = __expf(mrow[mt][1] - mn1);
            mrow[mt][0] = mn0; mrow[mt][1] = mn1;

            float sum0 = 0.f, sum1 = 0.f;
#pragma unroll
            for (int nt = 0; nt < 8; nt++) {
                float p0 = __expf(s[mt][nt][0] - mn0);
                float p1 = __expf(s[mt][nt][1] - mn0);
                float p2 = __expf(s[mt][nt][2] - mn1);
                float p3 = __expf(s[mt][nt][3] - mn1);
                sum0 += p0 + p1; sum1 += p2 + p3;
                ph[mt][nt][0] = pack_h2(p0, p1);
                ph[mt][nt][1] = pack_h2(p2, p3);
                o[mt][nt][0] *= al0; o[mt][nt][1] *= al0;
                o[mt][nt][2] *= al1; o[mt][nt][3] *= al1;
            }
            sum0 += __shfl_xor_sync(0xffffffffu, sum0, 1);
            sum0 += __shfl_xor_sync(0xffffffffu, sum0, 2);
            sum1 += __shfl_xor_sync(0xffffffffu, sum1, 1);
            sum1 += __shfl_xor_sync(0xffffffffu, sum1, 2);
            lrow[mt][0] = lrow[mt][0] * al0 + sum0;
            lrow[mt][1] = lrow[mt][1] * al1 + sum1;
        }

        // ---- O += P @ V  (register P; V pair-permutation matches ph) ----
#pragma unroll
        for (int kc = 0; kc < 4; kc++) {
            const int vcol = kc * 8 + 2 * tg;
#pragma unroll
            for (int nt = 0; nt < 8; nt++) {
                uint2 bf = *(const uint2*)&Vb[(nt * 8 + g) * VSTR + vcol];
#pragma unroll
                for (int mt = 0; mt < 2; mt++)
                    mma_fp16(o[mt][nt],
                             ph[mt][2 * kc][0], ph[mt][2 * kc][1],
                             ph[mt][2 * kc + 1][0], ph[mt][2 * kc + 1][1],
                             bf.x, bf.y);
            }
        }

        if (more) sts_V(nb, ea, eb);
        CP_WAIT(0);
        __syncthreads();
    }

    // ---- normalize + store ctx (half) ----
#pragma unroll
    for (int mt = 0; mt < 2; mt++) {
        const float li0 = 1.f / lrow[mt][0];
        const float li1 = 1.f / lrow[mt][1];
        const size_t r0 = baseC + (size_t)(qb * 128 + wr + mt * 16 + g) * DMODEL;
        const size_t r1 = r0 + (size_t)8 * DMODEL;
#pragma unroll
        for (int nt = 0; nt < 8; nt++) {
            const int col = nt * 8 + 2 * tg;
            *(uint32_t*)(C + r0 + col) = pack_h2(o[mt][nt][0] * li0, o[mt][nt][1] * li0);
            *(uint32_t*)(C + r1 + col) = pack_h2(o[mt][nt][2] * li1, o[mt][nt][3] * li1);
        }
    }
}

// ---------------------------------------------------------------------------
// Launch
// ---------------------------------------------------------------------------
extern "C" void kernel_launch(void* const* d_in, const int* in_sizes, int n_in,
                              void* d_out, int out_size)
{
    const float* X  = (const float*)d_in[0];
    const float* Wq = (const float*)d_in[1];
    const float* bq = (const float*)d_in[2];
    const float* Wk = (const float*)d_in[3];
    const float* bk = (const float*)d_in[4];
    const float* Wv = (const float*)d_in[5];
    const float* bv = (const float*)d_in[6];
    const float* Wo = (const float*)d_in[7];
    const float* bo = (const float*)d_in[8];
    float* out = (float*)d_out;

    __half *QKVp, *Cp, *Xh, *Wh;
    float* biasQKV;
    cudaGetSymbolAddress((void**)&QKVp, g_QKVh);
    cudaGetSymbolAddress((void**)&Cp, g_Ch);
    cudaGetSymbolAddress((void**)&Xh, g_Xh);
    cudaGetSymbolAddress((void**)&Wh, g_Wh);
    cudaGetSymbolAddress((void**)&biasQKV, g_biasQKV);
    __half* Wh0 = Wh;
    __half* Wh3 = Wh + 3 * (size_t)DMODEL * DMODEL;

    static bool attr_set = false;
    if (!attr_set) {
        cudaFuncSetAttribute(attention_tc,
                             cudaFuncAttributeMaxDynamicSharedMemorySize,
                             ATT_SMEM_U32 * (int)sizeof(uint32_t));
        cudaFuncSetAttribute(gemm_f16_nt<0>,
                             cudaFuncAttributeMaxDynamicSharedMemorySize,
                             GEMM_SMEM_BYTES);
        cudaFuncSetAttribute(gemm_f16_nt<1>,
                             cudaFuncAttributeMaxDynamicSharedMemorySize,
                             GEMM_SMEM_BYTES);
        attr_set = true;
    }

    cudaMemcpyAsync(biasQKV,            bq, DMODEL * sizeof(float), cudaMemcpyDeviceToDevice);
    cudaMemcpyAsync(biasQKV + DMODEL,   bk, DMODEL * sizeof(float), cudaMemcpyDeviceToDevice);
    cudaMemcpyAsync(biasQKV + 2*DMODEL, bv, DMODEL * sizeof(float), cudaMemcpyDeviceToDevice);

    const int XBLK = (MROWS * DMODEL) / (256 * 4);
    const int WBLK = (DMODEL * DMODEL) / (256 * 4);
    cvt_f32_f16<<<XBLK, 256>>>(X,  Xh);
    cvt_f32_f16<<<WBLK, 256>>>(Wq, Wh0);
    cvt_f32_f16<<<WBLK, 256>>>(Wk, Wh0 + (size_t)DMODEL * DMODEL);
    cvt_f32_f16<<<WBLK, 256>>>(Wv, Wh0 + 2 * (size_t)DMODEL * DMODEL);
    cvt_f32_f16<<<WBLK, 256>>>(Wo, Wh3);

    dim3 qkv_grid(NQKV / 128, MROWS / 128);      // (24, 128)
    gemm_f16_nt<0><<<qkv_grid, 128, GEMM_SMEM_BYTES>>>(
        Xh, Wh0, biasQKV, QKVp, MROWS, NQKV, DMODEL);

    dim3 att_grid(SEQ / 128, NHEAD, BATCH);      // (8, 16, 16)
    attention_tc<<<att_grid, 128, ATT_SMEM_U32 * sizeof(uint32_t)>>>(QKVp, Cp);

    dim3 o_grid(DMODEL / 128, MROWS / 128);      // (8, 128)
    gemm_f16_nt<1><<<o_grid, 128, GEMM_SMEM_BYTES>>>(
        Cp, Wh3, bo, out, MROWS, DMODEL, DMODEL);
}